// round 14
// baseline (speedup 1.0000x reference)
#include <cuda_runtime.h>
#include <cuda_fp16.h>
#include <cstdint>

#define NTOK  32768
#define HDIM  1024
#define HRDIM 512
#define CDIM  4096
#define NSTRIP (CDIM / 128)

#define A_L 8192       // one A limb tile: 128x32 fp16
#define B_L 8192       // one B limb tile: 128x32 fp16

using f16 = __half;

// ---------------- global limb planes + scratch (allocation-free) ------------
__device__ f16 g_xh[(size_t)NTOK * HDIM],  g_xl[(size_t)NTOK * HDIM];
__device__ f16 g_h1h[(size_t)NTOK * HDIM], g_h1l[(size_t)NTOK * HDIM];
__device__ f16 g_zh[(size_t)NTOK * HRDIM];
__device__ f16 g_qh[(size_t)NTOK * HRDIM], g_ql[(size_t)NTOK * HRDIM];
__device__ f16 g_h2h[(size_t)NTOK * HDIM], g_h2l[(size_t)NTOK * HDIM];
__device__ f16 g_cbh[(size_t)CDIM * HRDIM];
__device__ f16 g_w1h[1024 * 1024], g_w1l[1024 * 1024];
__device__ f16 g_w2h[512 * 1024],  g_w2l[512 * 1024];
__device__ f16 g_w3h[1024 * 512],  g_w3l[1024 * 512];
__device__ f16 g_w4h[1024 * 1024], g_w4l[1024 * 1024];
__device__ float g_z[(size_t)NTOK * HRDIM];
__device__ int   g_idx[NTOK];
__device__ float g_cnorm[CDIM];
__device__ float g_part[NTOK];
__device__ float g_pval[(size_t)NTOK * NSTRIP * 2];
__device__ int   g_pidx[(size_t)NTOK * NSTRIP * 2];

// ===================== PTX primitives =======================================
__device__ __forceinline__ uint32_t smem_to_u32(const void* p) {
    uint32_t a;
    asm("{ .reg .u64 t; cvta.to.shared.u64 t, %1; cvt.u32.u64 %0, t; }" : "=r"(a) : "l"(p));
    return a;
}
__device__ __forceinline__ void ldm4(uint32_t* r, uint32_t addr) {
    asm volatile("ldmatrix.sync.aligned.m8n8.x4.shared.b16 {%0,%1,%2,%3}, [%4];"
                 : "=r"(r[0]), "=r"(r[1]), "=r"(r[2]), "=r"(r[3]) : "r"(addr));
}
__device__ __forceinline__ void mma16816(float* c, const uint32_t* a, const uint32_t* b) {
    asm volatile("mma.sync.aligned.m16n8k16.row.col.f32.f16.f16.f32 "
                 "{%0,%1,%2,%3},{%4,%5,%6,%7},{%8,%9},{%0,%1,%2,%3};"
                 : "+f"(c[0]), "+f"(c[1]), "+f"(c[2]), "+f"(c[3])
                 : "r"(a[0]), "r"(a[1]), "r"(a[2]), "r"(a[3]), "r"(b[0]), "r"(b[1]));
}
__device__ __forceinline__ void cp16(uint32_t dst, const void* src) {
    asm volatile("cp.async.cg.shared.global [%0], [%1], 16;" :: "r"(dst), "l"(src) : "memory");
}
#define CP_COMMIT() asm volatile("cp.async.commit_group;" ::: "memory")
#define CP_WAIT1()  asm volatile("cp.async.wait_group 1;" ::: "memory")

// 64B-row swizzle (BK=32 tiles)
__device__ __forceinline__ uint32_t swz(int row, int ch) {
    return (uint32_t)(row * 64 + ((ch ^ ((row >> 1) & 3)) << 4));
}
// 128B-row swizzle (BK=64 tiles), conflict-free for ldsm + cp.async
__device__ __forceinline__ uint32_t swz128(int row, int ch) {
    return (uint32_t)(row * 128 + ((ch ^ (row & 7)) << 4));
}
__device__ __forceinline__ uint32_t packh2(float lo, float hi) {
    uint32_t p;
    asm("cvt.rn.f16x2.f32 %0, %1, %2;" : "=r"(p) : "f"(hi), "f"(lo));
    return p;
}
// exact fp16 2-limb split of a pair (residual ~2^-24)
__device__ __forceinline__ void splitf16(float a, float b, uint32_t& hp, uint32_t& lp) {
    const float ha = __half2float(__float2half_rn(a));
    const float hb = __half2float(__float2half_rn(b));
    hp = packh2(ha, hb);
    lp = packh2(a - ha, b - hb);
}

// ---------------- stage loader: cp.async fp16 limb tiles (128x32) -----------
template <int NL>
__device__ __forceinline__ void issue_stage(
    const f16* a0, const f16* a1, const f16* b0, const f16* b1,
    int ld, int bm, int bn, int k0, uint32_t ss, int tid)
{
    const f16* ap[2] = { a0, a1 };
    const f16* bp[2] = { b0, b1 };
#pragma unroll
    for (int i = 0; i < NL * 2; i++) {
        const int id = tid + i * 256;
        const int la = i >> 1;
        const int rem = id & 511;
        const int row = rem >> 2, ch = rem & 3;
        const char* g = (const char*)(ap[la] + (size_t)(bm + row) * ld + k0) + ch * 16;
        cp16(ss + la * A_L + swz(row, ch), g);
    }
#pragma unroll
    for (int i = 0; i < NL * 2; i++) {
        const int id = tid + i * 256;
        const int lb = i >> 1;
        const int rem = id & 511;
        const int row = rem >> 2, ch = rem & 3;
        const char* g = (const char*)(bp[lb] + (size_t)(bn + row) * ld + k0) + ch * 16;
        cp16(ss + NL * A_L + lb * B_L + swz(row, ch), g);
    }
}

// ---------------- one BK=32 stage of limb-pass MMAs -------------------------
// NPASS=4: hh,hl,lh,ll; NPASS=3: hh,hl,lh.
template <int NPASS>
__device__ __forceinline__ void compute_stage(uint32_t ss, int lane, int wm, int wn,
                                              float acc[2][8][4])
{
    constexpr int NL  = 2;
    const int arow = lane & 15, ach = lane >> 4;
    const int brow = (lane & 7) + ((lane >> 4) << 3), bch = (lane >> 3) & 1;
#pragma unroll
    for (int ks = 0; ks < 2; ks++) {
        uint32_t af[NL][2][4];
#pragma unroll
        for (int la = 0; la < NL; la++)
#pragma unroll
            for (int mt = 0; mt < 2; mt++)
                ldm4(af[la][mt], ss + la * A_L + swz(wm * 32 + mt * 16 + arow, ks * 2 + ach));
#pragma unroll
        for (int lb = 0; lb < NL; lb++) {
            uint32_t bf[4][4];
            const uint32_t bb = ss + NL * A_L + lb * B_L;
#pragma unroll
            for (int np = 0; np < 4; np++)
                ldm4(bf[np], bb + swz(wn * 64 + np * 16 + brow, ks * 2 + bch));
#pragma unroll
            for (int la = 0; la < NL; la++) {
                if (NPASS == 3 && la == 1 && lb == 1) continue;
#pragma unroll
                for (int mt = 0; mt < 2; mt++)
#pragma unroll
                    for (int nt = 0; nt < 8; nt++)
                        mma16816(acc[mt][nt], af[la][mt], &bf[nt >> 1][(nt & 1) * 2]);
            }
        }
    }
}

// ---------------- mainloop: 3-stage cp.async ring (BK=32, 2-limb) -----------
template <int K, int NPASS>
__device__ __forceinline__ void run_mainloop(
    const f16* a0, const f16* a1, const f16* b0, const f16* b1,
    int bm, int bn, char* sm, float acc[2][8][4])
{
    constexpr int NKT = K / 32;
    constexpr int NL  = 2;
    constexpr int STG = NL * (A_L + B_L);
    const int tid = threadIdx.x, lane = tid & 31, warp = tid >> 5;
    const int wm = warp >> 1, wn = warp & 1;
    const uint32_t sb = smem_to_u32(sm);

#pragma unroll
    for (int mt = 0; mt < 2; mt++)
#pragma unroll
        for (int nt = 0; nt < 8; nt++)
#pragma unroll
            for (int q = 0; q < 4; q++) acc[mt][nt][q] = 0.f;

    issue_stage<NL>(a0, a1, b0, b1, K, bm, bn, 0,  sb,       tid);
    CP_COMMIT();
    issue_stage<NL>(a0, a1, b0, b1, K, bm, bn, 32, sb + STG, tid);
    CP_COMMIT();

    int sc = 0, si = 2;
    for (int t = 0; t < NKT; t++) {
        CP_WAIT1();
        __syncthreads();
        if (t + 2 < NKT)
            issue_stage<NL>(a0, a1, b0, b1, K, bm, bn, (t + 2) * 32, sb + si * STG, tid);
        CP_COMMIT();
        compute_stage<NPASS>(sb + sc * STG, lane, wm, wn, acc);
        sc = (sc + 1 == 3) ? 0 : sc + 1;
        si = (si + 1 == 3) ? 0 : si + 1;
    }
}

// ---------------- BK=64 single-limb path (distance screening) ---------------
__device__ __forceinline__ void issue_stage64(
    const f16* a, const f16* b, int ld, int bm, int bn, int k0, uint32_t ss, int tid)
{
#pragma unroll
    for (int i = 0; i < 4; i++) {                 // A: 1024 16B chunks
        const int id = tid + i * 256;
        const int row = id >> 3, ch = id & 7;
        const char* g = (const char*)(a + (size_t)(bm + row) * ld + k0) + ch * 16;
        cp16(ss + swz128(row, ch), g);
    }
#pragma unroll
    for (int i = 0; i < 4; i++) {                 // B: 1024 16B chunks
        const int id = tid + i * 256;
        const int row = id >> 3, ch = id & 7;
        const char* g = (const char*)(b + (size_t)(bn + row) * ld + k0) + ch * 16;
        cp16(ss + 16384 + swz128(row, ch), g);
    }
}

__device__ __forceinline__ void compute_stage64(uint32_t ss, int lane, int wm, int wn,
                                                float acc[2][8][4])
{
    const int arow = lane & 15, ach = lane >> 4;
    const int brow = (lane & 7) + ((lane >> 4) << 3), bch = (lane >> 3) & 1;
#pragma unroll
    for (int ks = 0; ks < 4; ks++) {
        uint32_t af[2][4];
#pragma unroll
        for (int mt = 0; mt < 2; mt++)
            ldm4(af[mt], ss + swz128(wm * 32 + mt * 16 + arow, ks * 2 + ach));
        uint32_t bf[4][4];
#pragma unroll
        for (int np = 0; np < 4; np++)
            ldm4(bf[np], ss + 16384 + swz128(wn * 64 + np * 16 + brow, ks * 2 + bch));
#pragma unroll
        for (int mt = 0; mt < 2; mt++)
#pragma unroll
            for (int nt = 0; nt < 8; nt++)
                mma16816(acc[mt][nt], af[mt], &bf[nt >> 1][(nt & 1) * 2]);
    }
}

template <int K>
__device__ __forceinline__ void run_mainloop64(
    const f16* a, const f16* b, int bm, int bn, char* sm, float acc[2][8][4])
{
    constexpr int NKT = K / 64;
    constexpr int STG = 32768;
    const int tid = threadIdx.x, lane = tid & 31, warp = tid >> 5;
    const int wm = warp >> 1, wn = warp & 1;
    const uint32_t sb = smem_to_u32(sm);

#pragma unroll
    for (int mt = 0; mt < 2; mt++)
#pragma unroll
        for (int nt = 0; nt < 8; nt++)
#pragma unroll
            for (int q = 0; q < 4; q++) acc[mt][nt][q] = 0.f;

    issue_stage64(a, b, K, bm, bn, 0,  sb,       tid);
    CP_COMMIT();
    issue_stage64(a, b, K, bm, bn, 64, sb + STG, tid);
    CP_COMMIT();

    int sc = 0, si = 2;
    for (int t = 0; t < NKT; t++) {
        CP_WAIT1();
        __syncthreads();
        if (t + 2 < NKT)
            issue_stage64(a, b, K, bm, bn, (t + 2) * 64, sb + si * STG, tid);
        CP_COMMIT();
        compute_stage64(sb + sc * STG, lane, wm, wn, acc);
        sc = (sc + 1 == 3) ? 0 : sc + 1;
        si = (si + 1 == 3) ? 0 : si + 1;
    }
}

// ---------------- dense GEMM: [relu](A@B^T+bias) -> fp32 and/or limb planes -
template <int K, int NPASS, bool RELU, bool WF32, int NLOUT>
__global__ __launch_bounds__(256, 2)
void tgemm_kernel(const f16* a0, const f16* a1, const f16* b0, const f16* b1,
                  const float* __restrict__ bias, float* __restrict__ Cf,
                  f16* __restrict__ Ch, f16* __restrict__ Cl, int N)
{
    extern __shared__ char sm[];
    float acc[2][8][4];
    const int bm = blockIdx.y * 128, bn = blockIdx.x * 128;
    run_mainloop<K, NPASS>(a0, a1, b0, b1, bm, bn, sm, acc);

    const int tid = threadIdx.x, lane = tid & 31, warp = tid >> 5;
    const int wm = warp >> 1, wn = warp & 1;
#pragma unroll
    for (int mt = 0; mt < 2; mt++) {
        const int r0 = bm + wm * 32 + mt * 16 + (lane >> 2);
#pragma unroll
        for (int nt = 0; nt < 8; nt++) {
            const int c0 = bn + wn * 64 + nt * 8 + (lane & 3) * 2;
            const float bb0 = bias[c0], bb1 = bias[c0 + 1];
            float v00 = acc[mt][nt][0] + bb0, v01 = acc[mt][nt][1] + bb1;
            float v10 = acc[mt][nt][2] + bb0, v11 = acc[mt][nt][3] + bb1;
            if (RELU) {
                v00 = v00 > 0.f ? v00 : 0.f;  v01 = v01 > 0.f ? v01 : 0.f;
                v10 = v10 > 0.f ? v10 : 0.f;  v11 = v11 > 0.f ? v11 : 0.f;
            }
            if (WF32) {
                *(float2*)(Cf + (size_t)r0 * N + c0)       = make_float2(v00, v01);
                *(float2*)(Cf + (size_t)(r0 + 8) * N + c0) = make_float2(v10, v11);
            }
            if (NLOUT == 1) {
                *(uint32_t*)(Ch + (size_t)r0 * N + c0)       = packh2(v00, v01);
                *(uint32_t*)(Ch + (size_t)(r0 + 8) * N + c0) = packh2(v10, v11);
            }
            if (NLOUT == 2) {
                uint32_t h0, l0, h1, l1;
                splitf16(v00, v01, h0, l0);
                splitf16(v10, v11, h1, l1);
                *(uint32_t*)(Ch + (size_t)r0 * N + c0)       = h0;
                *(uint32_t*)(Ch + (size_t)(r0 + 8) * N + c0) = h1;
                *(uint32_t*)(Cl + (size_t)r0 * N + c0)       = l0;
                *(uint32_t*)(Cl + (size_t)(r0 + 8) * N + c0) = l1;
            }
        }
    }
}

// ---------------- approx distance (fp16 hh, BK=64) + top-2 per strip --------
__device__ __forceinline__ bool vless(float v, int i, float v2, int i2) {
    return v < v2 || (v == v2 && i < i2);
}

__global__ __launch_bounds__(256, 2)
void tdist_kernel(const f16* zh, const f16* cbh)
{
    extern __shared__ char sm[];
    float acc[2][8][4];
    const int strip = blockIdx.x;
    const int bn = strip * 128, bm = blockIdx.y * 128;
    run_mainloop64<HRDIM>(zh, cbh, bm, bn, sm, acc);

    const int tid = threadIdx.x, lane = tid & 31, warp = tid >> 5;
    const int wm = warp >> 1, wn = warp & 1;

    float t0[4], t1[4];
    int   ti0[4], ti1[4];
#pragma unroll
    for (int s = 0; s < 4; s++) { t0[s] = t1[s] = 3.4e38f; ti0[s] = ti1[s] = 0x7fffffff; }

#pragma unroll
    for (int mt = 0; mt < 2; mt++) {
#pragma unroll
        for (int nt = 0; nt < 8; nt++) {
            const int c0 = bn + wn * 64 + nt * 8 + (lane & 3) * 2;
            const float cn0 = g_cnorm[c0], cn1 = g_cnorm[c0 + 1];
            const float sc[4] = { cn0 - 2.f * acc[mt][nt][0], cn1 - 2.f * acc[mt][nt][1],
                                  cn0 - 2.f * acc[mt][nt][2], cn1 - 2.f * acc[mt][nt][3] };
            const int   ci[4] = { c0, c0 + 1, c0, c0 + 1 };
#pragma unroll
            for (int q = 0; q < 4; q++) {
                const int s = 2 * mt + (q >> 1);
                const float v = sc[q]; const int i = ci[q];
                if (vless(v, i, t0[s], ti0[s])) {
                    t1[s] = t0[s]; ti1[s] = ti0[s]; t0[s] = v; ti0[s] = i;
                } else if (vless(v, i, t1[s], ti1[s])) {
                    t1[s] = v; ti1[s] = i;
                }
            }
        }
    }
#pragma unroll
    for (int d = 1; d < 4; d <<= 1) {
#pragma unroll
        for (int s = 0; s < 4; s++) {
            float ov0 = __shfl_xor_sync(0xffffffffu, t0[s], d);
            int   oi0 = __shfl_xor_sync(0xffffffffu, ti0[s], d);
            float ov1 = __shfl_xor_sync(0xffffffffu, t1[s], d);
            int   oi1 = __shfl_xor_sync(0xffffffffu, ti1[s], d);
            if (vless(ov0, oi0, t0[s], ti0[s])) {
                float n1; int ni1;
                if (vless(t0[s], ti0[s], ov1, oi1)) { n1 = t0[s]; ni1 = ti0[s]; }
                else                                { n1 = ov1;   ni1 = oi1; }
                t0[s] = ov0; ti0[s] = oi0; t1[s] = n1; ti1[s] = ni1;
            } else {
                if (vless(ov0, oi0, t1[s], ti1[s])) { t1[s] = ov0; ti1[s] = oi0; }
            }
        }
    }
    __syncthreads();
    float* sv0 = (float*)sm;
    float* sv1 = sv0 + 256;
    int*   si0 = (int*)(sv1 + 256);
    int*   si1 = si0 + 256;
    if ((lane & 3) == 0) {
#pragma unroll
        for (int s = 0; s < 4; s++) {
            const int rloc = wm * 32 + (s >> 1) * 16 + (s & 1) * 8 + (lane >> 2);
            sv0[wn * 128 + rloc] = t0[s];  si0[wn * 128 + rloc] = ti0[s];
            sv1[wn * 128 + rloc] = t1[s];  si1[wn * 128 + rloc] = ti1[s];
        }
    }
    __syncthreads();
    if (tid < 128) {
        float a0 = sv0[tid], a1 = sv1[tid];
        int   ai0 = si0[tid], ai1 = si1[tid];
        const float b0v = sv0[128 + tid], b1v = sv1[128 + tid];
        const int   bi0 = si0[128 + tid], bi1 = si1[128 + tid];
        float r0, r1; int ri0, ri1;
        if (vless(a0, ai0, b0v, bi0)) {
            r0 = a0; ri0 = ai0;
            if (vless(a1, ai1, b0v, bi0)) { r1 = a1; ri1 = ai1; }
            else                          { r1 = b0v; ri1 = bi0; }
        } else {
            r0 = b0v; ri0 = bi0;
            if (vless(b1v, bi1, a0, ai0)) { r1 = b1v; ri1 = bi1; }
            else                          { r1 = a0;  ri1 = ai0; }
        }
        const int tok = bm + tid;
        const size_t base = (size_t)tok * (NSTRIP * 2) + strip * 2;
        g_pval[base] = r0;     g_pidx[base] = ri0;
        g_pval[base + 1] = r1; g_pidx[base + 1] = ri1;
    }
}

// ---------------- refine: exact fp64 rescoring of 8 best candidates ---------
__global__ __launch_bounds__(256, 4)
void refine_kernel(const float* __restrict__ z, const float* __restrict__ cb)
{
    const int warp = threadIdx.x >> 5, lane = threadIdx.x & 31;
    const int tok = blockIdx.x * 8 + warp;

    const float* pv = g_pval + (size_t)tok * (NSTRIP * 2);
    const int*   pi = g_pidx + (size_t)tok * (NSTRIP * 2);
    float v[2];
    int   id[2];
    v[0] = pv[lane];       id[0] = pi[lane];
    v[1] = pv[lane + 32];  id[1] = pi[lane + 32];

    const float* zr = z + (size_t)tok * HRDIM;
    double bestd = 1.0e300;
    int    besti = 0x7fffffff;

#pragma unroll 1
    for (int c = 0; c < 8; c++) {
        float mv = v[0]; int mi = id[0];
        if (vless(v[1], id[1], mv, mi)) { mv = v[1]; mi = id[1]; }
#pragma unroll
        for (int d = 16; d > 0; d >>= 1) {
            float ov = __shfl_xor_sync(0xffffffffu, mv, d);
            int   oi = __shfl_xor_sync(0xffffffffu, mi, d);
            if (vless(ov, oi, mv, mi)) { mv = ov; mi = oi; }
        }
        if (id[0] == mi) v[0] = 3.4e38f;
        if (id[1] == mi) v[1] = 3.4e38f;

        const float* e = cb + (size_t)mi * HRDIM;
        double acc = 0.0;
#pragma unroll
        for (int k = 0; k < HRDIM / 32; k++) {
            const int kk = lane + k * 32;
            const double df = (double)zr[kk] - (double)e[kk];
            acc += df * df;
        }
#pragma unroll
        for (int d = 16; d > 0; d >>= 1)
            acc += __shfl_xor_sync(0xffffffffu, acc, d);
        if (acc < bestd || (acc == bestd && mi < besti)) { bestd = acc; besti = mi; }
    }
    if (lane == 0) g_idx[tok] = besti;
}

// ---------------- input split: x -> 2 fp16 limb planes ----------------------
__global__ void splitx_kernel(const float4* __restrict__ in,
                              uint2* __restrict__ h, uint2* __restrict__ l)
{
    const size_t i = (size_t)blockIdx.x * 256 + threadIdx.x;
    const float4 v = in[i];
    uint32_t h0, l0, h1, l1;
    splitf16(v.x, v.y, h0, l0);
    splitf16(v.z, v.w, h1, l1);
    h[i] = make_uint2(h0, h1);
    l[i] = make_uint2(l0, l1);
}

// ---------------- codebook: norms + fp16 hi plane ---------------------------
__global__ void cbprep_kernel(const float* __restrict__ cb, uint2* __restrict__ h)
{
    __shared__ float s[128];
    const int c = blockIdx.x, t = threadIdx.x;
    const float4 v = ((const float4*)(cb + (size_t)c * HRDIM))[t];
    h[(size_t)c * (HRDIM / 4) + t] = make_uint2(packh2(v.x, v.y), packh2(v.z, v.w));
    s[t] = v.x * v.x + v.y * v.y + v.z * v.z + v.w * v.w;
    __syncthreads();
    for (int off = 64; off > 0; off >>= 1) {
        if (t < off) s[t] += s[t + off];
        __syncthreads();
    }
    if (t == 0) g_cnorm[c] = s[0];
}

// ---------------- weights: transpose + fp16 2-limb split --------------------
__global__ void transsplit_kernel(const float* __restrict__ in,
                                  f16* __restrict__ h, f16* __restrict__ l,
                                  int K, int N)
{
    __shared__ float t[32][33];
    const int n0 = blockIdx.x * 32, k0 = blockIdx.y * 32;
    const int tx = threadIdx.x, ty = threadIdx.y;
#pragma unroll
    for (int i = 0; i < 4; i++)
        t[ty + i * 8][tx] = in[(size_t)(k0 + ty + i * 8) * N + n0 + tx];
    __syncthreads();
#pragma unroll
    for (int i = 0; i < 4; i++) {
        const float a = t[tx][ty + i * 8];
        const float ha = __half2float(__float2half_rn(a));
        const size_t o = (size_t)(n0 + ty + i * 8) * K + k0 + tx;
        h[o] = __float2half_rn(ha);
        l[o] = __float2half_rn(a - ha);
    }
}

// ---------------- gather + STE + commit partials + q limbs ------------------
__global__ void gather_kernel(const float* __restrict__ CB,
                              float* __restrict__ outq,
                              float* __restrict__ outidx,
                              uint2* __restrict__ qh, uint2* __restrict__ ql)
{
    __shared__ float s[128];
    const int n = blockIdx.x;
    const int t = threadIdx.x;
    const int id = g_idx[n];

    float4 z4 = *(const float4*)(g_z + (size_t)n * HRDIM + t * 4);
    float4 q4 = *(const float4*)(CB + (size_t)id * HRDIM + t * 4);

    float4 o;
    o.x = z4.x + (q4.x - z4.x);
    o.y = z4.y + (q4.y - z4.y);
    o.z = z4.z + (q4.z - z4.z);
    o.w = z4.w + (q4.w - z4.w);
    *(float4*)(outq + (size_t)n * HRDIM + t * 4) = o;

    uint32_t h0, l0, h1, l1;
    splitf16(o.x, o.y, h0, l0);
    splitf16(o.z, o.w, h1, l1);
    const size_t qo = (size_t)n * (HRDIM / 4) + t;
    qh[qo] = make_uint2(h0, h1);
    ql[qo] = make_uint2(l0, l1);

    float dx = z4.x - q4.x, dy = z4.y - q4.y, dz = z4.z - q4.z, dw = z4.w - q4.w;
    s[t] = dx * dx + dy * dy + dz * dz + dw * dw;
    __syncthreads();
    for (int off = 64; off > 0; off >>= 1) {
        if (t < off) s[t] += s[t + off];
        __syncthreads();
    }
    if (t == 0) {
        g_part[n] = s[0];
        outidx[n] = (float)id;
    }
}

// ---------------- deterministic commit-loss sum -----------------------------
__global__ void losssum_kernel(float* __restrict__ outloss)
{
    __shared__ float s[1024];
    float acc = 0.f;
    for (int i = threadIdx.x; i < NTOK; i += 1024) acc += g_part[i];
    s[threadIdx.x] = acc;
    __syncthreads();
    for (int off = 512; off > 0; off >>= 1) {
        if (threadIdx.x < off) s[threadIdx.x] += s[threadIdx.x + off];
        __syncthreads();
    }
    if (threadIdx.x == 0)
        outloss[0] = 0.25f * s[0] / (float)((size_t)NTOK * HRDIM);
}

// ---------------- launch ----------------------------------------------------
extern "C" void kernel_launch(void* const* d_in, const int* in_sizes, int n_in,
                              void* d_out, int out_size)
{
    const float* x   = (const float*)d_in[0];
    const float* ew1 = (const float*)d_in[1];
    const float* eb1 = (const float*)d_in[2];
    const float* ew2 = (const float*)d_in[3];
    const float* eb2 = (const float*)d_in[4];
    const float* cb  = (const float*)d_in[5];
    const float* dw1 = (const float*)d_in[6];
    const float* db1 = (const float*)d_in[7];
    const float* dw2 = (const float*)d_in[8];
    const float* db2 = (const float*)d_in[9];

    float* out       = (float*)d_out;
    float* out_recon = out;
    float* out_q     = out + (size_t)NTOK * HDIM;
    float* out_idx   = out_q + (size_t)NTOK * HRDIM;
    float* out_loss  = out_idx + NTOK;

    f16 *xh, *xl, *h1h, *h1l, *zh, *qh, *ql, *h2h, *h2l, *cbh;
    f16 *w1h, *w1l, *w2h, *w2l, *w3h, *w3l, *w4h, *w4l;
    float* z;
    cudaGetSymbolAddress((void**)&xh, g_xh);   cudaGetSymbolAddress((void**)&xl, g_xl);
    cudaGetSymbolAddress((void**)&h1h, g_h1h); cudaGetSymbolAddress((void**)&h1l, g_h1l);
    cudaGetSymbolAddress((void**)&zh, g_zh);
    cudaGetSymbolAddress((void**)&qh, g_qh);   cudaGetSymbolAddress((void**)&ql, g_ql);
    cudaGetSymbolAddress((void**)&h2h, g_h2h); cudaGetSymbolAddress((void**)&h2l, g_h2l);
    cudaGetSymbolAddress((void**)&cbh, g_cbh);
    cudaGetSymbolAddress((void**)&w1h, g_w1h); cudaGetSymbolAddress((void**)&w1l, g_w1l);
    cudaGetSymbolAddress((void**)&w2h, g_w2h); cudaGetSymbolAddress((void**)&w2l, g_w2l);
    cudaGetSymbolAddress((void**)&w3h, g_w3h); cudaGetSymbolAddress((void**)&w3l, g_w3l);
    cudaGetSymbolAddress((void**)&w4h, g_w4h); cudaGetSymbolAddress((void**)&w4l, g_w4l);
    cudaGetSymbolAddress((void**)&z, g_z);

    const int SM2 = 3 * 2 * (A_L + B_L);   // 98304 (NL=2 ring)
    const int SMD = 3 * 32768;             // 98304 (BK=64 single-limb ring)

    cudaFuncSetAttribute(tgemm_kernel<1024, 3, true,  false, 2>, cudaFuncAttributeMaxDynamicSharedMemorySize, SM2);
    cudaFuncSetAttribute(tgemm_kernel<1024, 3, false, true,  1>, cudaFuncAttributeMaxDynamicSharedMemorySize, SM2);
    cudaFuncSetAttribute(tgemm_kernel<512,  3, true,  false, 2>, cudaFuncAttributeMaxDynamicSharedMemorySize, SM2);
    cudaFuncSetAttribute(tgemm_kernel<1024, 3, false, true,  0>, cudaFuncAttributeMaxDynamicSharedMemorySize, SM2);
    cudaFuncSetAttribute(tdist_kernel, cudaFuncAttributeMaxDynamicSharedMemorySize, SMD);

    // prep
    cbprep_kernel<<<CDIM, 128>>>(cb, (uint2*)cbh);
    splitx_kernel<<<(NTOK * HDIM / 4) / 256, 256>>>((const float4*)x, (uint2*)xh, (uint2*)xl);
    dim3 tb(32, 8);
    transsplit_kernel<<<dim3(32, 32), tb>>>(ew1, w1h, w1l, 1024, 1024);
    transsplit_kernel<<<dim3(16, 32), tb>>>(ew2, w2h, w2l, 1024, 512);
    transsplit_kernel<<<dim3(32, 16), tb>>>(dw1, w3h, w3l, 512, 1024);
    transsplit_kernel<<<dim3(32, 32), tb>>>(dw2, w4h, w4l, 1024, 1024);

    // encoder: 3-pass fp16 2-limb (dropped ll term ~2^-22 relative)
    tgemm_kernel<1024, 3, true, false, 2><<<dim3(8, NTOK / 128), 256, SM2>>>(
        xh, xl, w1h, w1l, eb1, nullptr, h1h, h1l, HDIM);
    tgemm_kernel<1024, 3, false, true, 1><<<dim3(4, NTOK / 128), 256, SM2>>>(
        h1h, h1l, w2h, w2l, eb2, z, zh, nullptr, HRDIM);

    // approx distance screening (fp16 hh, BK=64) + exact refine
    tdist_kernel<<<dim3(NSTRIP, NTOK / 128), 256, SMD>>>(zh, cbh);
    refine_kernel<<<NTOK / 8, 256>>>(z, cb);

    // quantized_st + q limbs + commit partials + indices + loss
    gather_kernel<<<NTOK, 128>>>(cb, out_q, out_idx, (uint2*)qh, (uint2*)ql);
    losssum_kernel<<<1, 1024>>>(out_loss);

    // decoder: 3-pass fp16
    tgemm_kernel<512, 3, true, false, 2><<<dim3(8, NTOK / 128), 256, SM2>>>(
        qh, ql, w3h, w3l, db1, nullptr, h2h, h2l, HDIM);
    tgemm_kernel<1024, 3, false, true, 0><<<dim3(8, NTOK / 128), 256, SM2>>>(
        h2h, h2l, w4h, w4l, db2, out_recon, nullptr, nullptr, HDIM);
}

// round 15
// speedup vs baseline: 1.5809x; 1.5809x over previous
#include <cuda_runtime.h>
#include <cuda_fp16.h>
#include <cstdint>

#define NTOK  32768
#define HDIM  1024
#define HRDIM 512
#define CDIM  4096
#define NSTRIP (CDIM / 128)

#define A_L 8192       // one A limb tile: 128x32 fp16
#define B_L 8192       // one B limb tile: 128x32 fp16

using f16 = __half;

// ---------------- global limb planes + scratch (allocation-free) ------------
__device__ f16 g_xh[(size_t)NTOK * HDIM],  g_xl[(size_t)NTOK * HDIM];
__device__ f16 g_h1h[(size_t)NTOK * HDIM], g_h1l[(size_t)NTOK * HDIM];
__device__ f16 g_zh[(size_t)NTOK * HRDIM];
__device__ f16 g_qh[(size_t)NTOK * HRDIM], g_ql[(size_t)NTOK * HRDIM];
__device__ f16 g_h2h[(size_t)NTOK * HDIM], g_h2l[(size_t)NTOK * HDIM];
__device__ f16 g_cbh[(size_t)CDIM * HRDIM];
__device__ f16 g_w1h[1024 * 1024], g_w1l[1024 * 1024];
__device__ f16 g_w2h[512 * 1024],  g_w2l[512 * 1024];
__device__ f16 g_w3h[1024 * 512],  g_w3l[1024 * 512];
__device__ f16 g_w4h[1024 * 1024], g_w4l[1024 * 1024];
__device__ float g_z[(size_t)NTOK * HRDIM];
__device__ int   g_idx[NTOK];
__device__ float g_cnorm[CDIM];
__device__ float g_part[NTOK];
__device__ float g_pval[(size_t)NTOK * NSTRIP * 2];
__device__ int   g_pidx[(size_t)NTOK * NSTRIP * 2];

// ===================== PTX primitives =======================================
__device__ __forceinline__ uint32_t smem_to_u32(const void* p) {
    uint32_t a;
    asm("{ .reg .u64 t; cvta.to.shared.u64 t, %1; cvt.u32.u64 %0, t; }" : "=r"(a) : "l"(p));
    return a;
}
__device__ __forceinline__ void ldm4(uint32_t* r, uint32_t addr) {
    asm volatile("ldmatrix.sync.aligned.m8n8.x4.shared.b16 {%0,%1,%2,%3}, [%4];"
                 : "=r"(r[0]), "=r"(r[1]), "=r"(r[2]), "=r"(r[3]) : "r"(addr));
}
__device__ __forceinline__ void mma16816(float* c, const uint32_t* a, const uint32_t* b) {
    asm volatile("mma.sync.aligned.m16n8k16.row.col.f32.f16.f16.f32 "
                 "{%0,%1,%2,%3},{%4,%5,%6,%7},{%8,%9},{%0,%1,%2,%3};"
                 : "+f"(c[0]), "+f"(c[1]), "+f"(c[2]), "+f"(c[3])
                 : "r"(a[0]), "r"(a[1]), "r"(a[2]), "r"(a[3]), "r"(b[0]), "r"(b[1]));
}
__device__ __forceinline__ void cp16(uint32_t dst, const void* src) {
    asm volatile("cp.async.cg.shared.global [%0], [%1], 16;" :: "r"(dst), "l"(src) : "memory");
}
#define CP_COMMIT() asm volatile("cp.async.commit_group;" ::: "memory")
#define CP_WAIT1()  asm volatile("cp.async.wait_group 1;" ::: "memory")

// 64B-row swizzle (BK=32 tiles)
__device__ __forceinline__ uint32_t swz(int row, int ch) {
    return (uint32_t)(row * 64 + ((ch ^ ((row >> 1) & 3)) << 4));
}
__device__ __forceinline__ uint32_t packh2(float lo, float hi) {
    uint32_t p;
    asm("cvt.rn.f16x2.f32 %0, %1, %2;" : "=r"(p) : "f"(hi), "f"(lo));
    return p;
}
// exact fp16 2-limb split of a pair (residual ~2^-24)
__device__ __forceinline__ void splitf16(float a, float b, uint32_t& hp, uint32_t& lp) {
    const float ha = __half2float(__float2half_rn(a));
    const float hb = __half2float(__float2half_rn(b));
    hp = packh2(ha, hb);
    lp = packh2(a - ha, b - hb);
}

// ---------------- stage loader: cp.async fp16 limb tiles (128x32) -----------
template <int NL>
__device__ __forceinline__ void issue_stage(
    const f16* a0, const f16* a1, const f16* b0, const f16* b1,
    int ld, int bm, int bn, int k0, uint32_t ss, int tid)
{
    const f16* ap[2] = { a0, a1 };
    const f16* bp[2] = { b0, b1 };
#pragma unroll
    for (int i = 0; i < NL * 2; i++) {
        const int id = tid + i * 256;
        const int la = i >> 1;
        const int rem = id & 511;
        const int row = rem >> 2, ch = rem & 3;
        const char* g = (const char*)(ap[la] + (size_t)(bm + row) * ld + k0) + ch * 16;
        cp16(ss + la * A_L + swz(row, ch), g);
    }
#pragma unroll
    for (int i = 0; i < NL * 2; i++) {
        const int id = tid + i * 256;
        const int lb = i >> 1;
        const int rem = id & 511;
        const int row = rem >> 2, ch = rem & 3;
        const char* g = (const char*)(bp[lb] + (size_t)(bn + row) * ld + k0) + ch * 16;
        cp16(ss + NL * A_L + lb * B_L + swz(row, ch), g);
    }
}

// ---------------- one BK=32 stage of limb-pass MMAs -------------------------
// NPASS=4: hh,hl,lh,ll; NPASS=3: hh,hl,lh; NPASS=1: hh.
template <int NPASS>
__device__ __forceinline__ void compute_stage(uint32_t ss, int lane, int wm, int wn,
                                              float acc[2][8][4])
{
    constexpr int NL  = (NPASS >= 3) ? 2 : 1;
    const int arow = lane & 15, ach = lane >> 4;
    const int brow = (lane & 7) + ((lane >> 4) << 3), bch = (lane >> 3) & 1;
#pragma unroll
    for (int ks = 0; ks < 2; ks++) {
        uint32_t af[NL][2][4];
#pragma unroll
        for (int la = 0; la < NL; la++)
#pragma unroll
            for (int mt = 0; mt < 2; mt++)
                ldm4(af[la][mt], ss + la * A_L + swz(wm * 32 + mt * 16 + arow, ks * 2 + ach));
#pragma unroll
        for (int lb = 0; lb < NL; lb++) {
            uint32_t bf[4][4];
            const uint32_t bb = ss + NL * A_L + lb * B_L;
#pragma unroll
            for (int np = 0; np < 4; np++)
                ldm4(bf[np], bb + swz(wn * 64 + np * 16 + brow, ks * 2 + bch));
#pragma unroll
            for (int la = 0; la < NL; la++) {
                if (NPASS == 3 && la == 1 && lb == 1) continue;
#pragma unroll
                for (int mt = 0; mt < 2; mt++)
#pragma unroll
                    for (int nt = 0; nt < 8; nt++)
                        mma16816(acc[mt][nt], af[la][mt], &bf[nt >> 1][(nt & 1) * 2]);
            }
        }
    }
}

// ---------------- mainloop: 3-stage cp.async ring ---------------------------
template <int K, int NPASS>
__device__ __forceinline__ void run_mainloop(
    const f16* a0, const f16* a1, const f16* b0, const f16* b1,
    int bm, int bn, char* sm, float acc[2][8][4])
{
    constexpr int NKT = K / 32;
    constexpr int NL  = (NPASS >= 3) ? 2 : 1;
    constexpr int STG = NL * (A_L + B_L);
    const int tid = threadIdx.x, lane = tid & 31, warp = tid >> 5;
    const int wm = warp >> 1, wn = warp & 1;
    const uint32_t sb = smem_to_u32(sm);

#pragma unroll
    for (int mt = 0; mt < 2; mt++)
#pragma unroll
        for (int nt = 0; nt < 8; nt++)
#pragma unroll
            for (int q = 0; q < 4; q++) acc[mt][nt][q] = 0.f;

    issue_stage<NL>(a0, a1, b0, b1, K, bm, bn, 0,  sb,       tid);
    CP_COMMIT();
    issue_stage<NL>(a0, a1, b0, b1, K, bm, bn, 32, sb + STG, tid);
    CP_COMMIT();

    int sc = 0, si = 2;
    for (int t = 0; t < NKT; t++) {
        CP_WAIT1();
        __syncthreads();
        if (t + 2 < NKT)
            issue_stage<NL>(a0, a1, b0, b1, K, bm, bn, (t + 2) * 32, sb + si * STG, tid);
        CP_COMMIT();
        compute_stage<NPASS>(sb + sc * STG, lane, wm, wn, acc);
        sc = (sc + 1 == 3) ? 0 : sc + 1;
        si = (si + 1 == 3) ? 0 : si + 1;
    }
}

// ---------------- dense GEMM: [relu](A@B^T+bias) -> fp32 and/or limb planes -
template <int K, int NPASS, bool RELU, bool WF32, int NLOUT>
__global__ __launch_bounds__(256, 2)
void tgemm_kernel(const f16* a0, const f16* a1, const f16* b0, const f16* b1,
                  const float* __restrict__ bias, float* __restrict__ Cf,
                  f16* __restrict__ Ch, f16* __restrict__ Cl, int N)
{
    extern __shared__ char sm[];
    float acc[2][8][4];
    const int bm = blockIdx.y * 128, bn = blockIdx.x * 128;
    run_mainloop<K, NPASS>(a0, a1, b0, b1, bm, bn, sm, acc);

    const int tid = threadIdx.x, lane = tid & 31, warp = tid >> 5;
    const int wm = warp >> 1, wn = warp & 1;
#pragma unroll
    for (int mt = 0; mt < 2; mt++) {
        const int r0 = bm + wm * 32 + mt * 16 + (lane >> 2);
#pragma unroll
        for (int nt = 0; nt < 8; nt++) {
            const int c0 = bn + wn * 64 + nt * 8 + (lane & 3) * 2;
            const float bb0 = bias[c0], bb1 = bias[c0 + 1];
            float v00 = acc[mt][nt][0] + bb0, v01 = acc[mt][nt][1] + bb1;
            float v10 = acc[mt][nt][2] + bb0, v11 = acc[mt][nt][3] + bb1;
            if (RELU) {
                v00 = v00 > 0.f ? v00 : 0.f;  v01 = v01 > 0.f ? v01 : 0.f;
                v10 = v10 > 0.f ? v10 : 0.f;  v11 = v11 > 0.f ? v11 : 0.f;
            }
            if (WF32) {
                *(float2*)(Cf + (size_t)r0 * N + c0)       = make_float2(v00, v01);
                *(float2*)(Cf + (size_t)(r0 + 8) * N + c0) = make_float2(v10, v11);
            }
            if (NLOUT == 1) {
                *(uint32_t*)(Ch + (size_t)r0 * N + c0)       = packh2(v00, v01);
                *(uint32_t*)(Ch + (size_t)(r0 + 8) * N + c0) = packh2(v10, v11);
            }
            if (NLOUT == 2) {
                uint32_t h0, l0, h1, l1;
                splitf16(v00, v01, h0, l0);
                splitf16(v10, v11, h1, l1);
                *(uint32_t*)(Ch + (size_t)r0 * N + c0)       = h0;
                *(uint32_t*)(Ch + (size_t)(r0 + 8) * N + c0) = h1;
                *(uint32_t*)(Cl + (size_t)r0 * N + c0)       = l0;
                *(uint32_t*)(Cl + (size_t)(r0 + 8) * N + c0) = l1;
            }
        }
    }
}

// ---------------- approx distance (fp16 hh) + top-2 per strip ---------------
__device__ __forceinline__ bool vless(float v, int i, float v2, int i2) {
    return v < v2 || (v == v2 && i < i2);
}

__global__ __launch_bounds__(256, 2)
void tdist_kernel(const f16* zh, const f16* cbh)
{
    extern __shared__ char sm[];
    float acc[2][8][4];
    const int strip = blockIdx.x;
    const int bn = strip * 128, bm = blockIdx.y * 128;
    run_mainloop<HRDIM, 1>(zh, zh, cbh, cbh, bm, bn, sm, acc);

    const int tid = threadIdx.x, lane = tid & 31, warp = tid >> 5;
    const int wm = warp >> 1, wn = warp & 1;

    float t0[4], t1[4];
    int   ti0[4], ti1[4];
#pragma unroll
    for (int s = 0; s < 4; s++) { t0[s] = t1[s] = 3.4e38f; ti0[s] = ti1[s] = 0x7fffffff; }

#pragma unroll
    for (int mt = 0; mt < 2; mt++) {
#pragma unroll
        for (int nt = 0; nt < 8; nt++) {
            const int c0 = bn + wn * 64 + nt * 8 + (lane & 3) * 2;
            const float cn0 = g_cnorm[c0], cn1 = g_cnorm[c0 + 1];
            const float sc[4] = { cn0 - 2.f * acc[mt][nt][0], cn1 - 2.f * acc[mt][nt][1],
                                  cn0 - 2.f * acc[mt][nt][2], cn1 - 2.f * acc[mt][nt][3] };
            const int   ci[4] = { c0, c0 + 1, c0, c0 + 1 };
#pragma unroll
            for (int q = 0; q < 4; q++) {
                const int s = 2 * mt + (q >> 1);
                const float v = sc[q]; const int i = ci[q];
                if (vless(v, i, t0[s], ti0[s])) {
                    t1[s] = t0[s]; ti1[s] = ti0[s]; t0[s] = v; ti0[s] = i;
                } else if (vless(v, i, t1[s], ti1[s])) {
                    t1[s] = v; ti1[s] = i;
                }
            }
        }
    }
#pragma unroll
    for (int d = 1; d < 4; d <<= 1) {
#pragma unroll
        for (int s = 0; s < 4; s++) {
            float ov0 = __shfl_xor_sync(0xffffffffu, t0[s], d);
            int   oi0 = __shfl_xor_sync(0xffffffffu, ti0[s], d);
            float ov1 = __shfl_xor_sync(0xffffffffu, t1[s], d);
            int   oi1 = __shfl_xor_sync(0xffffffffu, ti1[s], d);
            if (vless(ov0, oi0, t0[s], ti0[s])) {
                float n1; int ni1;
                if (vless(t0[s], ti0[s], ov1, oi1)) { n1 = t0[s]; ni1 = ti0[s]; }
                else                                { n1 = ov1;   ni1 = oi1; }
                t0[s] = ov0; ti0[s] = oi0; t1[s] = n1; ti1[s] = ni1;
            } else {
                if (vless(ov0, oi0, t1[s], ti1[s])) { t1[s] = ov0; ti1[s] = oi0; }
            }
        }
    }
    __syncthreads();
    float* sv0 = (float*)sm;
    float* sv1 = sv0 + 256;
    int*   si0 = (int*)(sv1 + 256);
    int*   si1 = si0 + 256;
    if ((lane & 3) == 0) {
#pragma unroll
        for (int s = 0; s < 4; s++) {
            const int rloc = wm * 32 + (s >> 1) * 16 + (s & 1) * 8 + (lane >> 2);
            sv0[wn * 128 + rloc] = t0[s];  si0[wn * 128 + rloc] = ti0[s];
            sv1[wn * 128 + rloc] = t1[s];  si1[wn * 128 + rloc] = ti1[s];
        }
    }
    __syncthreads();
    if (tid < 128) {
        float a0 = sv0[tid], a1 = sv1[tid];
        int   ai0 = si0[tid], ai1 = si1[tid];
        const float b0v = sv0[128 + tid], b1v = sv1[128 + tid];
        const int   bi0 = si0[128 + tid], bi1 = si1[128 + tid];
        float r0, r1; int ri0, ri1;
        if (vless(a0, ai0, b0v, bi0)) {
            r0 = a0; ri0 = ai0;
            if (vless(a1, ai1, b0v, bi0)) { r1 = a1; ri1 = ai1; }
            else                          { r1 = b0v; ri1 = bi0; }
        } else {
            r0 = b0v; ri0 = bi0;
            if (vless(b1v, bi1, a0, ai0)) { r1 = b1v; ri1 = bi1; }
            else                          { r1 = a0;  ri1 = ai0; }
        }
        const int tok = bm + tid;
        const size_t base = (size_t)tok * (NSTRIP * 2) + strip * 2;
        g_pval[base] = r0;     g_pidx[base] = ri0;
        g_pval[base + 1] = r1; g_pidx[base + 1] = ri1;
    }
}

// ---------------- refine: exact fp64 rescoring of 8 best candidates ---------
__global__ __launch_bounds__(256, 4)
void refine_kernel(const float* __restrict__ z, const float* __restrict__ cb)
{
    const int warp = threadIdx.x >> 5, lane = threadIdx.x & 31;
    const int tok = blockIdx.x * 8 + warp;

    const float* pv = g_pval + (size_t)tok * (NSTRIP * 2);
    const int*   pi = g_pidx + (size_t)tok * (NSTRIP * 2);
    float v[2];
    int   id[2];
    v[0] = pv[lane];       id[0] = pi[lane];
    v[1] = pv[lane + 32];  id[1] = pi[lane + 32];

    const float* zr = z + (size_t)tok * HRDIM;
    double bestd = 1.0e300;
    int    besti = 0x7fffffff;

#pragma unroll 1
    for (int c = 0; c < 8; c++) {
        float mv = v[0]; int mi = id[0];
        if (vless(v[1], id[1], mv, mi)) { mv = v[1]; mi = id[1]; }
#pragma unroll
        for (int d = 16; d > 0; d >>= 1) {
            float ov = __shfl_xor_sync(0xffffffffu, mv, d);
            int   oi = __shfl_xor_sync(0xffffffffu, mi, d);
            if (vless(ov, oi, mv, mi)) { mv = ov; mi = oi; }
        }
        if (id[0] == mi) v[0] = 3.4e38f;
        if (id[1] == mi) v[1] = 3.4e38f;

        const float* e = cb + (size_t)mi * HRDIM;
        double acc = 0.0;
#pragma unroll
        for (int k = 0; k < HRDIM / 32; k++) {
            const int kk = lane + k * 32;
            const double df = (double)zr[kk] - (double)e[kk];
            acc += df * df;
        }
#pragma unroll
        for (int d = 16; d > 0; d >>= 1)
            acc += __shfl_xor_sync(0xffffffffu, acc, d);
        if (acc < bestd || (acc == bestd && mi < besti)) { bestd = acc; besti = mi; }
    }
    if (lane == 0) g_idx[tok] = besti;
}

// ---------------- input split: x -> 2 fp16 limb planes ----------------------
__global__ void splitx_kernel(const float4* __restrict__ in,
                              uint2* __restrict__ h, uint2* __restrict__ l)
{
    const size_t i = (size_t)blockIdx.x * 256 + threadIdx.x;
    const float4 v = in[i];
    uint32_t h0, l0, h1, l1;
    splitf16(v.x, v.y, h0, l0);
    splitf16(v.z, v.w, h1, l1);
    h[i] = make_uint2(h0, h1);
    l[i] = make_uint2(l0, l1);
}

// ---------------- codebook: norms + fp16 hi plane ---------------------------
__global__ void cbprep_kernel(const float* __restrict__ cb, uint2* __restrict__ h)
{
    __shared__ float s[128];
    const int c = blockIdx.x, t = threadIdx.x;
    const float4 v = ((const float4*)(cb + (size_t)c * HRDIM))[t];
    h[(size_t)c * (HRDIM / 4) + t] = make_uint2(packh2(v.x, v.y), packh2(v.z, v.w));
    s[t] = v.x * v.x + v.y * v.y + v.z * v.z + v.w * v.w;
    __syncthreads();
    for (int off = 64; off > 0; off >>= 1) {
        if (t < off) s[t] += s[t + off];
        __syncthreads();
    }
    if (t == 0) g_cnorm[c] = s[0];
}

// ---------------- weights: transpose + fp16 2-limb split --------------------
__global__ void transsplit_kernel(const float* __restrict__ in,
                                  f16* __restrict__ h, f16* __restrict__ l,
                                  int K, int N)
{
    __shared__ float t[32][33];
    const int n0 = blockIdx.x * 32, k0 = blockIdx.y * 32;
    const int tx = threadIdx.x, ty = threadIdx.y;
#pragma unroll
    for (int i = 0; i < 4; i++)
        t[ty + i * 8][tx] = in[(size_t)(k0 + ty + i * 8) * N + n0 + tx];
    __syncthreads();
#pragma unroll
    for (int i = 0; i < 4; i++) {
        const float a = t[tx][ty + i * 8];
        const float ha = __half2float(__float2half_rn(a));
        const size_t o = (size_t)(n0 + ty + i * 8) * K + k0 + tx;
        h[o] = __float2half_rn(ha);
        l[o] = __float2half_rn(a - ha);
    }
}

// ---------------- gather + STE + commit partials + q limbs ------------------
__global__ void gather_kernel(const float* __restrict__ CB,
                              float* __restrict__ outq,
                              float* __restrict__ outidx,
                              uint2* __restrict__ qh, uint2* __restrict__ ql)
{
    __shared__ float s[128];
    const int n = blockIdx.x;
    const int t = threadIdx.x;
    const int id = g_idx[n];

    float4 z4 = *(const float4*)(g_z + (size_t)n * HRDIM + t * 4);
    float4 q4 = *(const float4*)(CB + (size_t)id * HRDIM + t * 4);

    float4 o;
    o.x = z4.x + (q4.x - z4.x);
    o.y = z4.y + (q4.y - z4.y);
    o.z = z4.z + (q4.z - z4.z);
    o.w = z4.w + (q4.w - z4.w);
    *(float4*)(outq + (size_t)n * HRDIM + t * 4) = o;

    uint32_t h0, l0, h1, l1;
    splitf16(o.x, o.y, h0, l0);
    splitf16(o.z, o.w, h1, l1);
    const size_t qo = (size_t)n * (HRDIM / 4) + t;
    qh[qo] = make_uint2(h0, h1);
    ql[qo] = make_uint2(l0, l1);

    float dx = z4.x - q4.x, dy = z4.y - q4.y, dz = z4.z - q4.z, dw = z4.w - q4.w;
    s[t] = dx * dx + dy * dy + dz * dz + dw * dw;
    __syncthreads();
    for (int off = 64; off > 0; off >>= 1) {
        if (t < off) s[t] += s[t + off];
        __syncthreads();
    }
    if (t == 0) {
        g_part[n] = s[0];
        outidx[n] = (float)id;
    }
}

// ---------------- deterministic commit-loss sum -----------------------------
__global__ void losssum_kernel(float* __restrict__ outloss)
{
    __shared__ float s[1024];
    float acc = 0.f;
    for (int i = threadIdx.x; i < NTOK; i += 1024) acc += g_part[i];
    s[threadIdx.x] = acc;
    __syncthreads();
    for (int off = 512; off > 0; off >>= 1) {
        if (threadIdx.x < off) s[threadIdx.x] += s[threadIdx.x + off];
        __syncthreads();
    }
    if (threadIdx.x == 0)
        outloss[0] = 0.25f * s[0] / (float)((size_t)NTOK * HRDIM);
}

// ---------------- launch ----------------------------------------------------
extern "C" void kernel_launch(void* const* d_in, const int* in_sizes, int n_in,
                              void* d_out, int out_size)
{
    const float* x   = (const float*)d_in[0];
    const float* ew1 = (const float*)d_in[1];
    const float* eb1 = (const float*)d_in[2];
    const float* ew2 = (const float*)d_in[3];
    const float* eb2 = (const float*)d_in[4];
    const float* cb  = (const float*)d_in[5];
    const float* dw1 = (const float*)d_in[6];
    const float* db1 = (const float*)d_in[7];
    const float* dw2 = (const float*)d_in[8];
    const float* db2 = (const float*)d_in[9];

    float* out       = (float*)d_out;
    float* out_recon = out;
    float* out_q     = out + (size_t)NTOK * HDIM;
    float* out_idx   = out_q + (size_t)NTOK * HRDIM;
    float* out_loss  = out_idx + NTOK;

    f16 *xh, *xl, *h1h, *h1l, *zh, *qh, *ql, *h2h, *h2l, *cbh;
    f16 *w1h, *w1l, *w2h, *w2l, *w3h, *w3l, *w4h, *w4l;
    float* z;
    cudaGetSymbolAddress((void**)&xh, g_xh);   cudaGetSymbolAddress((void**)&xl, g_xl);
    cudaGetSymbolAddress((void**)&h1h, g_h1h); cudaGetSymbolAddress((void**)&h1l, g_h1l);
    cudaGetSymbolAddress((void**)&zh, g_zh);
    cudaGetSymbolAddress((void**)&qh, g_qh);   cudaGetSymbolAddress((void**)&ql, g_ql);
    cudaGetSymbolAddress((void**)&h2h, g_h2h); cudaGetSymbolAddress((void**)&h2l, g_h2l);
    cudaGetSymbolAddress((void**)&cbh, g_cbh);
    cudaGetSymbolAddress((void**)&w1h, g_w1h); cudaGetSymbolAddress((void**)&w1l, g_w1l);
    cudaGetSymbolAddress((void**)&w2h, g_w2h); cudaGetSymbolAddress((void**)&w2l, g_w2l);
    cudaGetSymbolAddress((void**)&w3h, g_w3h); cudaGetSymbolAddress((void**)&w3l, g_w3l);
    cudaGetSymbolAddress((void**)&w4h, g_w4h); cudaGetSymbolAddress((void**)&w4l, g_w4l);
    cudaGetSymbolAddress((void**)&z, g_z);

    const int SM2 = 3 * 2 * (A_L + B_L);   // 98304 (NL=2 ring)
    const int SM1 = 3 * 1 * (A_L + B_L);   // 49152 (NL=1 ring)

    cudaFuncSetAttribute(tgemm_kernel<1024, 3, true,  false, 2>, cudaFuncAttributeMaxDynamicSharedMemorySize, SM2);
    cudaFuncSetAttribute(tgemm_kernel<1024, 3, false, true,  1>, cudaFuncAttributeMaxDynamicSharedMemorySize, SM2);
    cudaFuncSetAttribute(tgemm_kernel<512,  3, true,  false, 2>, cudaFuncAttributeMaxDynamicSharedMemorySize, SM2);
    cudaFuncSetAttribute(tgemm_kernel<1024, 3, false, true,  0>, cudaFuncAttributeMaxDynamicSharedMemorySize, SM2);
    cudaFuncSetAttribute(tdist_kernel, cudaFuncAttributeMaxDynamicSharedMemorySize, SM1);

    // prep
    cbprep_kernel<<<CDIM, 128>>>(cb, (uint2*)cbh);
    splitx_kernel<<<(NTOK * HDIM / 4) / 256, 256>>>((const float4*)x, (uint2*)xh, (uint2*)xl);
    dim3 tb(32, 8);
    transsplit_kernel<<<dim3(32, 32), tb>>>(ew1, w1h, w1l, 1024, 1024);
    transsplit_kernel<<<dim3(16, 32), tb>>>(ew2, w2h, w2l, 1024, 512);
    transsplit_kernel<<<dim3(32, 16), tb>>>(dw1, w3h, w3l, 512, 1024);
    transsplit_kernel<<<dim3(32, 32), tb>>>(dw2, w4h, w4l, 1024, 1024);

    // encoder: 3-pass fp16 2-limb (ll term dropped; error ~2^-22)
    tgemm_kernel<1024, 3, true, false, 2><<<dim3(8, NTOK / 128), 256, SM2>>>(
        xh, xl, w1h, w1l, eb1, nullptr, h1h, h1l, HDIM);
    tgemm_kernel<1024, 3, false, true, 1><<<dim3(4, NTOK / 128), 256, SM2>>>(
        h1h, h1l, w2h, w2l, eb2, z, zh, nullptr, HRDIM);

    // approx distance screening (fp16 hh, BK=32 — R13 path) + exact refine
    tdist_kernel<<<dim3(NSTRIP, NTOK / 128), 256, SM1>>>(zh, cbh);
    refine_kernel<<<NTOK / 8, 256>>>(z, cb);

    // quantized_st + q limbs + commit partials + indices + loss
    gather_kernel<<<NTOK, 128>>>(cb, out_q, out_idx, (uint2*)qh, (uint2*)ql);
    losssum_kernel<<<1, 1024>>>(out_loss);

    // decoder: 3-pass fp16
    tgemm_kernel<512, 3, true, false, 2><<<dim3(8, NTOK / 128), 256, SM2>>>(
        qh, ql, w3h, w3l, db1, nullptr, h2h, h2l, HDIM);
    tgemm_kernel<1024, 3, false, true, 0><<<dim3(8, NTOK / 128), 256, SM2>>>(
        h2h, h2l, w4h, w4l, db2, out_recon, nullptr, nullptr, HDIM);
}

// round 16
// speedup vs baseline: 1.9479x; 1.2321x over previous
#include <cuda_runtime.h>
#include <cuda_fp16.h>
#include <cstdint>

#define NTOK  32768
#define HDIM  1024
#define HRDIM 512
#define CDIM  4096
#define NSTRIP (CDIM / 128)

#define A_L 8192       // one A limb tile: 128x32 fp16
#define B_L 8192       // one B limb tile: 128x32 fp16

using f16 = __half;

// ---------------- global limb planes + scratch (allocation-free) ------------
__device__ f16 g_xh[(size_t)NTOK * HDIM],  g_xl[(size_t)NTOK * HDIM];
__device__ f16 g_h1h[(size_t)NTOK * HDIM], g_h1l[(size_t)NTOK * HDIM];
__device__ f16 g_zh[(size_t)NTOK * HRDIM];
__device__ f16 g_cbh[(size_t)CDIM * HRDIM], g_cbl[(size_t)CDIM * HRDIM];
__device__ f16 g_hch[(size_t)CDIM * HDIM],  g_hcl[(size_t)CDIM * HDIM];
__device__ float g_crec[(size_t)CDIM * HDIM];     // per-code recon [4096,1024]
__device__ f16 g_w1h[1024 * 1024], g_w1l[1024 * 1024];
__device__ f16 g_w2h[512 * 1024],  g_w2l[512 * 1024];
__device__ f16 g_w3h[1024 * 512],  g_w3l[1024 * 512];
__device__ f16 g_w4h[1024 * 1024], g_w4l[1024 * 1024];
__device__ float g_z[(size_t)NTOK * HRDIM];
__device__ int   g_idx[NTOK];
__device__ float g_cnorm[CDIM];
__device__ float g_part[NTOK];
__device__ float g_pval[(size_t)NTOK * NSTRIP * 2];
__device__ int   g_pidx[(size_t)NTOK * NSTRIP * 2];

// ===================== PTX primitives =======================================
__device__ __forceinline__ uint32_t smem_to_u32(const void* p) {
    uint32_t a;
    asm("{ .reg .u64 t; cvta.to.shared.u64 t, %1; cvt.u32.u64 %0, t; }" : "=r"(a) : "l"(p));
    return a;
}
__device__ __forceinline__ void ldm4(uint32_t* r, uint32_t addr) {
    asm volatile("ldmatrix.sync.aligned.m8n8.x4.shared.b16 {%0,%1,%2,%3}, [%4];"
                 : "=r"(r[0]), "=r"(r[1]), "=r"(r[2]), "=r"(r[3]) : "r"(addr));
}
__device__ __forceinline__ void mma16816(float* c, const uint32_t* a, const uint32_t* b) {
    asm volatile("mma.sync.aligned.m16n8k16.row.col.f32.f16.f16.f32 "
                 "{%0,%1,%2,%3},{%4,%5,%6,%7},{%8,%9},{%0,%1,%2,%3};"
                 : "+f"(c[0]), "+f"(c[1]), "+f"(c[2]), "+f"(c[3])
                 : "r"(a[0]), "r"(a[1]), "r"(a[2]), "r"(a[3]), "r"(b[0]), "r"(b[1]));
}
__device__ __forceinline__ void cp16(uint32_t dst, const void* src) {
    asm volatile("cp.async.cg.shared.global [%0], [%1], 16;" :: "r"(dst), "l"(src) : "memory");
}
#define CP_COMMIT() asm volatile("cp.async.commit_group;" ::: "memory")
#define CP_WAIT1()  asm volatile("cp.async.wait_group 1;" ::: "memory")

// 64B-row swizzle (BK=32 tiles)
__device__ __forceinline__ uint32_t swz(int row, int ch) {
    return (uint32_t)(row * 64 + ((ch ^ ((row >> 1) & 3)) << 4));
}
__device__ __forceinline__ uint32_t packh2(float lo, float hi) {
    uint32_t p;
    asm("cvt.rn.f16x2.f32 %0, %1, %2;" : "=r"(p) : "f"(hi), "f"(lo));
    return p;
}
// exact fp16 2-limb split of a pair (residual ~2^-24)
__device__ __forceinline__ void splitf16(float a, float b, uint32_t& hp, uint32_t& lp) {
    const float ha = __half2float(__float2half_rn(a));
    const float hb = __half2float(__float2half_rn(b));
    hp = packh2(ha, hb);
    lp = packh2(a - ha, b - hb);
}

// ---------------- stage loader: cp.async fp16 limb tiles (128x32) -----------
template <int NL>
__device__ __forceinline__ void issue_stage(
    const f16* a0, const f16* a1, const f16* b0, const f16* b1,
    int ld, int bm, int bn, int k0, uint32_t ss, int tid)
{
    const f16* ap[2] = { a0, a1 };
    const f16* bp[2] = { b0, b1 };
#pragma unroll
    for (int i = 0; i < NL * 2; i++) {
        const int id = tid + i * 256;
        const int la = i >> 1;
        const int rem = id & 511;
        const int row = rem >> 2, ch = rem & 3;
        const char* g = (const char*)(ap[la] + (size_t)(bm + row) * ld + k0) + ch * 16;
        cp16(ss + la * A_L + swz(row, ch), g);
    }
#pragma unroll
    for (int i = 0; i < NL * 2; i++) {
        const int id = tid + i * 256;
        const int lb = i >> 1;
        const int rem = id & 511;
        const int row = rem >> 2, ch = rem & 3;
        const char* g = (const char*)(bp[lb] + (size_t)(bn + row) * ld + k0) + ch * 16;
        cp16(ss + NL * A_L + lb * B_L + swz(row, ch), g);
    }
}

// ---------------- one BK=32 stage of limb-pass MMAs -------------------------
// NPASS=4: hh,hl,lh,ll; NPASS=3: hh,hl,lh; NPASS=1: hh.
template <int NPASS>
__device__ __forceinline__ void compute_stage(uint32_t ss, int lane, int wm, int wn,
                                              float acc[2][8][4])
{
    constexpr int NL  = (NPASS >= 3) ? 2 : 1;
    const int arow = lane & 15, ach = lane >> 4;
    const int brow = (lane & 7) + ((lane >> 4) << 3), bch = (lane >> 3) & 1;
#pragma unroll
    for (int ks = 0; ks < 2; ks++) {
        uint32_t af[NL][2][4];
#pragma unroll
        for (int la = 0; la < NL; la++)
#pragma unroll
            for (int mt = 0; mt < 2; mt++)
                ldm4(af[la][mt], ss + la * A_L + swz(wm * 32 + mt * 16 + arow, ks * 2 + ach));
#pragma unroll
        for (int lb = 0; lb < NL; lb++) {
            uint32_t bf[4][4];
            const uint32_t bb = ss + NL * A_L + lb * B_L;
#pragma unroll
            for (int np = 0; np < 4; np++)
                ldm4(bf[np], bb + swz(wn * 64 + np * 16 + brow, ks * 2 + bch));
#pragma unroll
            for (int la = 0; la < NL; la++) {
                if (NPASS == 3 && la == 1 && lb == 1) continue;
#pragma unroll
                for (int mt = 0; mt < 2; mt++)
#pragma unroll
                    for (int nt = 0; nt < 8; nt++)
                        mma16816(acc[mt][nt], af[la][mt], &bf[nt >> 1][(nt & 1) * 2]);
            }
        }
    }
}

// ---------------- mainloop: 3-stage cp.async ring ---------------------------
template <int K, int NPASS>
__device__ __forceinline__ void run_mainloop(
    const f16* a0, const f16* a1, const f16* b0, const f16* b1,
    int bm, int bn, char* sm, float acc[2][8][4])
{
    constexpr int NKT = K / 32;
    constexpr int NL  = (NPASS >= 3) ? 2 : 1;
    constexpr int STG = NL * (A_L + B_L);
    const int tid = threadIdx.x, lane = tid & 31, warp = tid >> 5;
    const int wm = warp >> 1, wn = warp & 1;
    const uint32_t sb = smem_to_u32(sm);

#pragma unroll
    for (int mt = 0; mt < 2; mt++)
#pragma unroll
        for (int nt = 0; nt < 8; nt++)
#pragma unroll
            for (int q = 0; q < 4; q++) acc[mt][nt][q] = 0.f;

    issue_stage<NL>(a0, a1, b0, b1, K, bm, bn, 0,  sb,       tid);
    CP_COMMIT();
    issue_stage<NL>(a0, a1, b0, b1, K, bm, bn, 32, sb + STG, tid);
    CP_COMMIT();

    int sc = 0, si = 2;
    for (int t = 0; t < NKT; t++) {
        CP_WAIT1();
        __syncthreads();
        if (t + 2 < NKT)
            issue_stage<NL>(a0, a1, b0, b1, K, bm, bn, (t + 2) * 32, sb + si * STG, tid);
        CP_COMMIT();
        compute_stage<NPASS>(sb + sc * STG, lane, wm, wn, acc);
        sc = (sc + 1 == 3) ? 0 : sc + 1;
        si = (si + 1 == 3) ? 0 : si + 1;
    }
}

// ---------------- dense GEMM: [relu](A@B^T+bias) -> fp32 and/or limb planes -
template <int K, int NPASS, bool RELU, bool WF32, int NLOUT>
__global__ __launch_bounds__(256, 2)
void tgemm_kernel(const f16* a0, const f16* a1, const f16* b0, const f16* b1,
                  const float* __restrict__ bias, float* __restrict__ Cf,
                  f16* __restrict__ Ch, f16* __restrict__ Cl, int N)
{
    extern __shared__ char sm[];
    float acc[2][8][4];
    const int bm = blockIdx.y * 128, bn = blockIdx.x * 128;
    run_mainloop<K, NPASS>(a0, a1, b0, b1, bm, bn, sm, acc);

    const int tid = threadIdx.x, lane = tid & 31, warp = tid >> 5;
    const int wm = warp >> 1, wn = warp & 1;
#pragma unroll
    for (int mt = 0; mt < 2; mt++) {
        const int r0 = bm + wm * 32 + mt * 16 + (lane >> 2);
#pragma unroll
        for (int nt = 0; nt < 8; nt++) {
            const int c0 = bn + wn * 64 + nt * 8 + (lane & 3) * 2;
            const float bb0 = bias[c0], bb1 = bias[c0 + 1];
            float v00 = acc[mt][nt][0] + bb0, v01 = acc[mt][nt][1] + bb1;
            float v10 = acc[mt][nt][2] + bb0, v11 = acc[mt][nt][3] + bb1;
            if (RELU) {
                v00 = v00 > 0.f ? v00 : 0.f;  v01 = v01 > 0.f ? v01 : 0.f;
                v10 = v10 > 0.f ? v10 : 0.f;  v11 = v11 > 0.f ? v11 : 0.f;
            }
            if (WF32) {
                *(float2*)(Cf + (size_t)r0 * N + c0)       = make_float2(v00, v01);
                *(float2*)(Cf + (size_t)(r0 + 8) * N + c0) = make_float2(v10, v11);
            }
            if (NLOUT == 1) {
                *(uint32_t*)(Ch + (size_t)r0 * N + c0)       = packh2(v00, v01);
                *(uint32_t*)(Ch + (size_t)(r0 + 8) * N + c0) = packh2(v10, v11);
            }
            if (NLOUT == 2) {
                uint32_t h0, l0, h1, l1;
                splitf16(v00, v01, h0, l0);
                splitf16(v10, v11, h1, l1);
                *(uint32_t*)(Ch + (size_t)r0 * N + c0)       = h0;
                *(uint32_t*)(Ch + (size_t)(r0 + 8) * N + c0) = h1;
                *(uint32_t*)(Cl + (size_t)r0 * N + c0)       = l0;
                *(uint32_t*)(Cl + (size_t)(r0 + 8) * N + c0) = l1;
            }
        }
    }
}

// ---------------- approx distance (fp16 hh) + top-2 per strip ---------------
__device__ __forceinline__ bool vless(float v, int i, float v2, int i2) {
    return v < v2 || (v == v2 && i < i2);
}

__global__ __launch_bounds__(256, 2)
void tdist_kernel(const f16* zh, const f16* cbh)
{
    extern __shared__ char sm[];
    float acc[2][8][4];
    const int strip = blockIdx.x;
    const int bn = strip * 128, bm = blockIdx.y * 128;
    run_mainloop<HRDIM, 1>(zh, zh, cbh, cbh, bm, bn, sm, acc);

    const int tid = threadIdx.x, lane = tid & 31, warp = tid >> 5;
    const int wm = warp >> 1, wn = warp & 1;

    float t0[4], t1[4];
    int   ti0[4], ti1[4];
#pragma unroll
    for (int s = 0; s < 4; s++) { t0[s] = t1[s] = 3.4e38f; ti0[s] = ti1[s] = 0x7fffffff; }

#pragma unroll
    for (int mt = 0; mt < 2; mt++) {
#pragma unroll
        for (int nt = 0; nt < 8; nt++) {
            const int c0 = bn + wn * 64 + nt * 8 + (lane & 3) * 2;
            const float cn0 = g_cnorm[c0], cn1 = g_cnorm[c0 + 1];
            const float sc[4] = { cn0 - 2.f * acc[mt][nt][0], cn1 - 2.f * acc[mt][nt][1],
                                  cn0 - 2.f * acc[mt][nt][2], cn1 - 2.f * acc[mt][nt][3] };
            const int   ci[4] = { c0, c0 + 1, c0, c0 + 1 };
#pragma unroll
            for (int q = 0; q < 4; q++) {
                const int s = 2 * mt + (q >> 1);
                const float v = sc[q]; const int i = ci[q];
                if (vless(v, i, t0[s], ti0[s])) {
                    t1[s] = t0[s]; ti1[s] = ti0[s]; t0[s] = v; ti0[s] = i;
                } else if (vless(v, i, t1[s], ti1[s])) {
                    t1[s] = v; ti1[s] = i;
                }
            }
        }
    }
#pragma unroll
    for (int d = 1; d < 4; d <<= 1) {
#pragma unroll
        for (int s = 0; s < 4; s++) {
            float ov0 = __shfl_xor_sync(0xffffffffu, t0[s], d);
            int   oi0 = __shfl_xor_sync(0xffffffffu, ti0[s], d);
            float ov1 = __shfl_xor_sync(0xffffffffu, t1[s], d);
            int   oi1 = __shfl_xor_sync(0xffffffffu, ti1[s], d);
            if (vless(ov0, oi0, t0[s], ti0[s])) {
                float n1; int ni1;
                if (vless(t0[s], ti0[s], ov1, oi1)) { n1 = t0[s]; ni1 = ti0[s]; }
                else                                { n1 = ov1;   ni1 = oi1; }
                t0[s] = ov0; ti0[s] = oi0; t1[s] = n1; ti1[s] = ni1;
            } else {
                if (vless(ov0, oi0, t1[s], ti1[s])) { t1[s] = ov0; ti1[s] = oi0; }
            }
        }
    }
    __syncthreads();
    float* sv0 = (float*)sm;
    float* sv1 = sv0 + 256;
    int*   si0 = (int*)(sv1 + 256);
    int*   si1 = si0 + 256;
    if ((lane & 3) == 0) {
#pragma unroll
        for (int s = 0; s < 4; s++) {
            const int rloc = wm * 32 + (s >> 1) * 16 + (s & 1) * 8 + (lane >> 2);
            sv0[wn * 128 + rloc] = t0[s];  si0[wn * 128 + rloc] = ti0[s];
            sv1[wn * 128 + rloc] = t1[s];  si1[wn * 128 + rloc] = ti1[s];
        }
    }
    __syncthreads();
    if (tid < 128) {
        float a0 = sv0[tid], a1 = sv1[tid];
        int   ai0 = si0[tid], ai1 = si1[tid];
        const float b0v = sv0[128 + tid], b1v = sv1[128 + tid];
        const int   bi0 = si0[128 + tid], bi1 = si1[128 + tid];
        float r0, r1; int ri0, ri1;
        if (vless(a0, ai0, b0v, bi0)) {
            r0 = a0; ri0 = ai0;
            if (vless(a1, ai1, b0v, bi0)) { r1 = a1; ri1 = ai1; }
            else                          { r1 = b0v; ri1 = bi0; }
        } else {
            r0 = b0v; ri0 = bi0;
            if (vless(b1v, bi1, a0, ai0)) { r1 = b1v; ri1 = bi1; }
            else                          { r1 = a0;  ri1 = ai0; }
        }
        const int tok = bm + tid;
        const size_t base = (size_t)tok * (NSTRIP * 2) + strip * 2;
        g_pval[base] = r0;     g_pidx[base] = ri0;
        g_pval[base + 1] = r1; g_pidx[base + 1] = ri1;
    }
}

// ---------------- refine: exact fp64 rescoring of 8 best candidates ---------
__global__ __launch_bounds__(256, 4)
void refine_kernel(const float* __restrict__ z, const float* __restrict__ cb)
{
    const int warp = threadIdx.x >> 5, lane = threadIdx.x & 31;
    const int tok = blockIdx.x * 8 + warp;

    const float* pv = g_pval + (size_t)tok * (NSTRIP * 2);
    const int*   pi = g_pidx + (size_t)tok * (NSTRIP * 2);
    float v[2];
    int   id[2];
    v[0] = pv[lane];       id[0] = pi[lane];
    v[1] = pv[lane + 32];  id[1] = pi[lane + 32];

    const float* zr = z + (size_t)tok * HRDIM;
    double bestd = 1.0e300;
    int    besti = 0x7fffffff;

#pragma unroll 1
    for (int c = 0; c < 8; c++) {
        float mv = v[0]; int mi = id[0];
        if (vless(v[1], id[1], mv, mi)) { mv = v[1]; mi = id[1]; }
#pragma unroll
        for (int d = 16; d > 0; d >>= 1) {
            float ov = __shfl_xor_sync(0xffffffffu, mv, d);
            int   oi = __shfl_xor_sync(0xffffffffu, mi, d);
            if (vless(ov, oi, mv, mi)) { mv = ov; mi = oi; }
        }
        if (id[0] == mi) v[0] = 3.4e38f;
        if (id[1] == mi) v[1] = 3.4e38f;

        const float* e = cb + (size_t)mi * HRDIM;
        double acc = 0.0;
#pragma unroll
        for (int k = 0; k < HRDIM / 32; k++) {
            const int kk = lane + k * 32;
            const double df = (double)zr[kk] - (double)e[kk];
            acc += df * df;
        }
#pragma unroll
        for (int d = 16; d > 0; d >>= 1)
            acc += __shfl_xor_sync(0xffffffffu, acc, d);
        if (acc < bestd || (acc == bestd && mi < besti)) { bestd = acc; besti = mi; }
    }
    if (lane == 0) g_idx[tok] = besti;
}

// ---------------- input split: x -> 2 fp16 limb planes ----------------------
__global__ void splitx_kernel(const float4* __restrict__ in,
                              uint2* __restrict__ h, uint2* __restrict__ l)
{
    const size_t i = (size_t)blockIdx.x * 256 + threadIdx.x;
    const float4 v = in[i];
    uint32_t h0, l0, h1, l1;
    splitf16(v.x, v.y, h0, l0);
    splitf16(v.z, v.w, h1, l1);
    h[i] = make_uint2(h0, h1);
    l[i] = make_uint2(l0, l1);
}

// ---------------- codebook: norms + fp16 2-limb planes ----------------------
__global__ void cbprep_kernel(const float* __restrict__ cb,
                              uint2* __restrict__ h, uint2* __restrict__ l)
{
    __shared__ float s[128];
    const int c = blockIdx.x, t = threadIdx.x;
    const float4 v = ((const float4*)(cb + (size_t)c * HRDIM))[t];
    uint32_t h0, l0, h1, l1;
    splitf16(v.x, v.y, h0, l0);
    splitf16(v.z, v.w, h1, l1);
    const size_t o = (size_t)c * (HRDIM / 4) + t;
    h[o] = make_uint2(h0, h1);
    l[o] = make_uint2(l0, l1);
    s[t] = v.x * v.x + v.y * v.y + v.z * v.z + v.w * v.w;
    __syncthreads();
    for (int off = 64; off > 0; off >>= 1) {
        if (t < off) s[t] += s[t + off];
        __syncthreads();
    }
    if (t == 0) g_cnorm[c] = s[0];
}

// ---------------- weights: transpose + fp16 2-limb split --------------------
__global__ void transsplit_kernel(const float* __restrict__ in,
                                  f16* __restrict__ h, f16* __restrict__ l,
                                  int K, int N)
{
    __shared__ float t[32][33];
    const int n0 = blockIdx.x * 32, k0 = blockIdx.y * 32;
    const int tx = threadIdx.x, ty = threadIdx.y;
#pragma unroll
    for (int i = 0; i < 4; i++)
        t[ty + i * 8][tx] = in[(size_t)(k0 + ty + i * 8) * N + n0 + tx];
    __syncthreads();
#pragma unroll
    for (int i = 0; i < 4; i++) {
        const float a = t[tx][ty + i * 8];
        const float ha = __half2float(__float2half_rn(a));
        const size_t o = (size_t)(n0 + ty + i * 8) * K + k0 + tx;
        h[o] = __float2half_rn(ha);
        l[o] = __float2half_rn(a - ha);
    }
}

// ---------------- gather + STE + commit partials + index write --------------
__global__ void gather_kernel(const float* __restrict__ CB,
                              float* __restrict__ outq,
                              float* __restrict__ outidx)
{
    __shared__ float s[128];
    const int n = blockIdx.x;
    const int t = threadIdx.x;
    const int id = g_idx[n];

    float4 z4 = *(const float4*)(g_z + (size_t)n * HRDIM + t * 4);
    float4 q4 = *(const float4*)(CB + (size_t)id * HRDIM + t * 4);

    float4 o;
    o.x = z4.x + (q4.x - z4.x);
    o.y = z4.y + (q4.y - z4.y);
    o.z = z4.z + (q4.z - z4.z);
    o.w = z4.w + (q4.w - z4.w);
    *(float4*)(outq + (size_t)n * HRDIM + t * 4) = o;

    float dx = z4.x - q4.x, dy = z4.y - q4.y, dz = z4.z - q4.z, dw = z4.w - q4.w;
    s[t] = dx * dx + dy * dy + dz * dz + dw * dw;
    __syncthreads();
    for (int off = 64; off > 0; off >>= 1) {
        if (t < off) s[t] += s[t + off];
        __syncthreads();
    }
    if (t == 0) {
        g_part[n] = s[0];
        outidx[n] = (float)id;
    }
}

// ---------------- recon gather: out_recon[token] = cb_recon[idx[token]] -----
__global__ void recon_gather_kernel(float* __restrict__ out_recon)
{
    const int n = blockIdx.x;
    const int t = threadIdx.x;
    const int id = g_idx[n];
    const float4 v = ((const float4*)(g_crec + (size_t)id * HDIM))[t];
    ((float4*)(out_recon + (size_t)n * HDIM))[t] = v;
}

// ---------------- deterministic commit-loss sum -----------------------------
__global__ void losssum_kernel(float* __restrict__ outloss)
{
    __shared__ float s[1024];
    float acc = 0.f;
    for (int i = threadIdx.x; i < NTOK; i += 1024) acc += g_part[i];
    s[threadIdx.x] = acc;
    __syncthreads();
    for (int off = 512; off > 0; off >>= 1) {
        if (threadIdx.x < off) s[threadIdx.x] += s[threadIdx.x + off];
        __syncthreads();
    }
    if (threadIdx.x == 0)
        outloss[0] = 0.25f * s[0] / (float)((size_t)NTOK * HRDIM);
}

// ---------------- launch ----------------------------------------------------
extern "C" void kernel_launch(void* const* d_in, const int* in_sizes, int n_in,
                              void* d_out, int out_size)
{
    const float* x   = (const float*)d_in[0];
    const float* ew1 = (const float*)d_in[1];
    const float* eb1 = (const float*)d_in[2];
    const float* ew2 = (const float*)d_in[3];
    const float* eb2 = (const float*)d_in[4];
    const float* cb  = (const float*)d_in[5];
    const float* dw1 = (const float*)d_in[6];
    const float* db1 = (const float*)d_in[7];
    const float* dw2 = (const float*)d_in[8];
    const float* db2 = (const float*)d_in[9];

    float* out       = (float*)d_out;
    float* out_recon = out;
    float* out_q     = out + (size_t)NTOK * HDIM;
    float* out_idx   = out_q + (size_t)NTOK * HRDIM;
    float* out_loss  = out_idx + NTOK;

    f16 *xh, *xl, *h1h, *h1l, *zh, *cbh, *cbl, *hch, *hcl;
    f16 *w1h, *w1l, *w2h, *w2l, *w3h, *w3l, *w4h, *w4l;
    float *z, *crec;
    cudaGetSymbolAddress((void**)&xh, g_xh);   cudaGetSymbolAddress((void**)&xl, g_xl);
    cudaGetSymbolAddress((void**)&h1h, g_h1h); cudaGetSymbolAddress((void**)&h1l, g_h1l);
    cudaGetSymbolAddress((void**)&zh, g_zh);
    cudaGetSymbolAddress((void**)&cbh, g_cbh); cudaGetSymbolAddress((void**)&cbl, g_cbl);
    cudaGetSymbolAddress((void**)&hch, g_hch); cudaGetSymbolAddress((void**)&hcl, g_hcl);
    cudaGetSymbolAddress((void**)&crec, g_crec);
    cudaGetSymbolAddress((void**)&w1h, g_w1h); cudaGetSymbolAddress((void**)&w1l, g_w1l);
    cudaGetSymbolAddress((void**)&w2h, g_w2h); cudaGetSymbolAddress((void**)&w2l, g_w2l);
    cudaGetSymbolAddress((void**)&w3h, g_w3h); cudaGetSymbolAddress((void**)&w3l, g_w3l);
    cudaGetSymbolAddress((void**)&w4h, g_w4h); cudaGetSymbolAddress((void**)&w4l, g_w4l);
    cudaGetSymbolAddress((void**)&z, g_z);

    const int SM2 = 3 * 2 * (A_L + B_L);   // 98304 (NL=2 ring)
    const int SM1 = 3 * 1 * (A_L + B_L);   // 49152 (NL=1 ring)

    cudaFuncSetAttribute(tgemm_kernel<1024, 3, true,  false, 2>, cudaFuncAttributeMaxDynamicSharedMemorySize, SM2);
    cudaFuncSetAttribute(tgemm_kernel<1024, 3, false, true,  1>, cudaFuncAttributeMaxDynamicSharedMemorySize, SM2);
    cudaFuncSetAttribute(tgemm_kernel<512,  3, true,  false, 2>, cudaFuncAttributeMaxDynamicSharedMemorySize, SM2);
    cudaFuncSetAttribute(tgemm_kernel<1024, 3, false, true,  0>, cudaFuncAttributeMaxDynamicSharedMemorySize, SM2);
    cudaFuncSetAttribute(tdist_kernel, cudaFuncAttributeMaxDynamicSharedMemorySize, SM1);

    // prep: splits + codebook planes/norms
    cbprep_kernel<<<CDIM, 128>>>(cb, (uint2*)cbh, (uint2*)cbl);
    splitx_kernel<<<(NTOK * HDIM / 4) / 256, 256>>>((const float4*)x, (uint2*)xh, (uint2*)xl);
    dim3 tb(32, 8);
    transsplit_kernel<<<dim3(32, 32), tb>>>(ew1, w1h, w1l, 1024, 1024);
    transsplit_kernel<<<dim3(16, 32), tb>>>(ew2, w2h, w2l, 1024, 512);
    transsplit_kernel<<<dim3(32, 16), tb>>>(dw1, w3h, w3l, 512, 1024);
    transsplit_kernel<<<dim3(32, 32), tb>>>(dw2, w4h, w4l, 1024, 1024);

    // decoder collapsed over the 4096-entry codebook (runs on exact cb rows):
    //   hc  = relu(cb @ dw1 + db1)    [4096,1024]
    //   crec = hc @ dw2 + db2         [4096,1024]
    tgemm_kernel<512, 3, true, false, 2><<<dim3(8, CDIM / 128), 256, SM2>>>(
        cbh, cbl, w3h, w3l, db1, nullptr, hch, hcl, HDIM);
    tgemm_kernel<1024, 3, false, true, 0><<<dim3(8, CDIM / 128), 256, SM2>>>(
        hch, hcl, w4h, w4l, db2, crec, nullptr, nullptr, HDIM);

    // encoder: 3-pass fp16 2-limb (ll term dropped; error ~2^-22)
    tgemm_kernel<1024, 3, true, false, 2><<<dim3(8, NTOK / 128), 256, SM2>>>(
        xh, xl, w1h, w1l, eb1, nullptr, h1h, h1l, HDIM);
    tgemm_kernel<1024, 3, false, true, 1><<<dim3(4, NTOK / 128), 256, SM2>>>(
        h1h, h1l, w2h, w2l, eb2, z, zh, nullptr, HRDIM);

    // approx distance screening (fp16 hh) + exact refine
    tdist_kernel<<<dim3(NSTRIP, NTOK / 128), 256, SM1>>>(zh, cbh);
    refine_kernel<<<NTOK / 8, 256>>>(z, cb);

    // quantized_st + commit partials + indices + loss
    gather_kernel<<<NTOK, 128>>>(cb, out_q, out_idx);
    losssum_kernel<<<1, 1024>>>(out_loss);

    // recon via per-code table gather
    recon_gather_kernel<<<NTOK, 256>>>(out_recon);
}

// round 17
// speedup vs baseline: 2.3430x; 1.2029x over previous
#include <cuda_runtime.h>
#include <cuda_fp16.h>
#include <cstdint>

#define NTOK  32768
#define HDIM  1024
#define HRDIM 512
#define CDIM  4096
#define NSTRIP 16              // 16 strips of 256 codes
#define NCAND  32              // 16 strips x top-2

#define A_L 8192               // one A limb tile: 128x32 fp16
#define B_L 8192               // one B limb tile: 128x32 fp16

using f16 = __half;

// ---------------- global limb planes + scratch (allocation-free) ------------
__device__ f16 g_xh[(size_t)NTOK * HDIM],  g_xl[(size_t)NTOK * HDIM];
__device__ f16 g_h1h[(size_t)NTOK * HDIM], g_h1l[(size_t)NTOK * HDIM];
__device__ f16 g_zh[(size_t)NTOK * HRDIM];
__device__ f16 g_cbh[(size_t)CDIM * HRDIM], g_cbl[(size_t)CDIM * HRDIM];
__device__ f16 g_hch[(size_t)CDIM * HDIM],  g_hcl[(size_t)CDIM * HDIM];
__device__ float g_crec[(size_t)CDIM * HDIM];     // per-code recon [4096,1024]
__device__ f16 g_w1h[1024 * 1024], g_w1l[1024 * 1024];
__device__ f16 g_w2h[512 * 1024],  g_w2l[512 * 1024];
__device__ f16 g_w3h[1024 * 512],  g_w3l[1024 * 512];
__device__ f16 g_w4h[1024 * 1024], g_w4l[1024 * 1024];
__device__ float g_z[(size_t)NTOK * HRDIM];
__device__ int   g_idx[NTOK];
__device__ float g_cnorm[CDIM];
__device__ float g_part[NTOK];
__device__ float g_pval[(size_t)NTOK * NCAND];
__device__ int   g_pidx[(size_t)NTOK * NCAND];

// ===================== PTX primitives =======================================
__device__ __forceinline__ uint32_t smem_to_u32(const void* p) {
    uint32_t a;
    asm("{ .reg .u64 t; cvta.to.shared.u64 t, %1; cvt.u32.u64 %0, t; }" : "=r"(a) : "l"(p));
    return a;
}
__device__ __forceinline__ void ldm4(uint32_t* r, uint32_t addr) {
    asm volatile("ldmatrix.sync.aligned.m8n8.x4.shared.b16 {%0,%1,%2,%3}, [%4];"
                 : "=r"(r[0]), "=r"(r[1]), "=r"(r[2]), "=r"(r[3]) : "r"(addr));
}
__device__ __forceinline__ void mma16816(float* c, const uint32_t* a, const uint32_t* b) {
    asm volatile("mma.sync.aligned.m16n8k16.row.col.f32.f16.f16.f32 "
                 "{%0,%1,%2,%3},{%4,%5,%6,%7},{%8,%9},{%0,%1,%2,%3};"
                 : "+f"(c[0]), "+f"(c[1]), "+f"(c[2]), "+f"(c[3])
                 : "r"(a[0]), "r"(a[1]), "r"(a[2]), "r"(a[3]), "r"(b[0]), "r"(b[1]));
}
__device__ __forceinline__ void cp16(uint32_t dst, const void* src) {
    asm volatile("cp.async.cg.shared.global [%0], [%1], 16;" :: "r"(dst), "l"(src) : "memory");
}
#define CP_COMMIT() asm volatile("cp.async.commit_group;" ::: "memory")
#define CP_WAIT1()  asm volatile("cp.async.wait_group 1;" ::: "memory")
#define CP_WAIT2()  asm volatile("cp.async.wait_group 2;" ::: "memory")

// 64B-row swizzle (BK=32 tiles)
__device__ __forceinline__ uint32_t swz(int row, int ch) {
    return (uint32_t)(row * 64 + ((ch ^ ((row >> 1) & 3)) << 4));
}
__device__ __forceinline__ uint32_t packh2(float lo, float hi) {
    uint32_t p;
    asm("cvt.rn.f16x2.f32 %0, %1, %2;" : "=r"(p) : "f"(hi), "f"(lo));
    return p;
}
// exact fp16 2-limb split of a pair (residual ~2^-24)
__device__ __forceinline__ void splitf16(float a, float b, uint32_t& hp, uint32_t& lp) {
    const float ha = __half2float(__float2half_rn(a));
    const float hb = __half2float(__float2half_rn(b));
    hp = packh2(ha, hb);
    lp = packh2(a - ha, b - hb);
}

// ---------------- stage loader: cp.async fp16 limb tiles (128x32) -----------
template <int NL>
__device__ __forceinline__ void issue_stage(
    const f16* a0, const f16* a1, const f16* b0, const f16* b1,
    int ld, int bm, int bn, int k0, uint32_t ss, int tid)
{
    const f16* ap[2] = { a0, a1 };
    const f16* bp[2] = { b0, b1 };
#pragma unroll
    for (int i = 0; i < NL * 2; i++) {
        const int id = tid + i * 256;
        const int la = i >> 1;
        const int rem = id & 511;
        const int row = rem >> 2, ch = rem & 3;
        const char* g = (const char*)(ap[la] + (size_t)(bm + row) * ld + k0) + ch * 16;
        cp16(ss + la * A_L + swz(row, ch), g);
    }
#pragma unroll
    for (int i = 0; i < NL * 2; i++) {
        const int id = tid + i * 256;
        const int lb = i >> 1;
        const int rem = id & 511;
        const int row = rem >> 2, ch = rem & 3;
        const char* g = (const char*)(bp[lb] + (size_t)(bn + row) * ld + k0) + ch * 16;
        cp16(ss + NL * A_L + lb * B_L + swz(row, ch), g);
    }
}

// ---------------- one BK=32 stage of limb-pass MMAs (dense GEMMs) -----------
// NPASS=4: hh,hl,lh,ll; NPASS=3: hh,hl,lh.
template <int NPASS>
__device__ __forceinline__ void compute_stage(uint32_t ss, int lane, int wm, int wn,
                                              float acc[2][8][4])
{
    constexpr int NL  = (NPASS >= 3) ? 2 : 1;
    const int arow = lane & 15, ach = lane >> 4;
    const int brow = (lane & 7) + ((lane >> 4) << 3), bch = (lane >> 3) & 1;
#pragma unroll
    for (int ks = 0; ks < 2; ks++) {
        uint32_t af[NL][2][4];
#pragma unroll
        for (int la = 0; la < NL; la++)
#pragma unroll
            for (int mt = 0; mt < 2; mt++)
                ldm4(af[la][mt], ss + la * A_L + swz(wm * 32 + mt * 16 + arow, ks * 2 + ach));
#pragma unroll
        for (int lb = 0; lb < NL; lb++) {
            uint32_t bf[4][4];
            const uint32_t bb = ss + NL * A_L + lb * B_L;
#pragma unroll
            for (int np = 0; np < 4; np++)
                ldm4(bf[np], bb + swz(wn * 64 + np * 16 + brow, ks * 2 + bch));
#pragma unroll
            for (int la = 0; la < NL; la++) {
                if (NPASS == 3 && la == 1 && lb == 1) continue;
#pragma unroll
                for (int mt = 0; mt < 2; mt++)
#pragma unroll
                    for (int nt = 0; nt < 8; nt++)
                        mma16816(acc[mt][nt], af[la][mt], &bf[nt >> 1][(nt & 1) * 2]);
            }
        }
    }
}

// ---------------- mainloop: 3-stage cp.async ring (dense GEMMs) -------------
template <int K, int NPASS>
__device__ __forceinline__ void run_mainloop(
    const f16* a0, const f16* a1, const f16* b0, const f16* b1,
    int bm, int bn, char* sm, float acc[2][8][4])
{
    constexpr int NKT = K / 32;
    constexpr int NL  = (NPASS >= 3) ? 2 : 1;
    constexpr int STG = NL * (A_L + B_L);
    const int tid = threadIdx.x, lane = tid & 31, warp = tid >> 5;
    const int wm = warp >> 1, wn = warp & 1;
    const uint32_t sb = smem_to_u32(sm);

#pragma unroll
    for (int mt = 0; mt < 2; mt++)
#pragma unroll
        for (int nt = 0; nt < 8; nt++)
#pragma unroll
            for (int q = 0; q < 4; q++) acc[mt][nt][q] = 0.f;

    issue_stage<NL>(a0, a1, b0, b1, K, bm, bn, 0,  sb,       tid);
    CP_COMMIT();
    issue_stage<NL>(a0, a1, b0, b1, K, bm, bn, 32, sb + STG, tid);
    CP_COMMIT();

    int sc = 0, si = 2;
    for (int t = 0; t < NKT; t++) {
        CP_WAIT1();
        __syncthreads();
        if (t + 2 < NKT)
            issue_stage<NL>(a0, a1, b0, b1, K, bm, bn, (t + 2) * 32, sb + si * STG, tid);
        CP_COMMIT();
        compute_stage<NPASS>(sb + sc * STG, lane, wm, wn, acc);
        sc = (sc + 1 == 3) ? 0 : sc + 1;
        si = (si + 1 == 3) ? 0 : si + 1;
    }
}

// ---------------- dense GEMM: [relu](A@B^T+bias) -> fp32 and/or limb planes -
template <int K, int NPASS, bool RELU, bool WF32, int NLOUT>
__global__ __launch_bounds__(256, 2)
void tgemm_kernel(const f16* a0, const f16* a1, const f16* b0, const f16* b1,
                  const float* __restrict__ bias, float* __restrict__ Cf,
                  f16* __restrict__ Ch, f16* __restrict__ Cl, int N)
{
    extern __shared__ char sm[];
    float acc[2][8][4];
    const int bm = blockIdx.y * 128, bn = blockIdx.x * 128;
    run_mainloop<K, NPASS>(a0, a1, b0, b1, bm, bn, sm, acc);

    const int tid = threadIdx.x, lane = tid & 31, warp = tid >> 5;
    const int wm = warp >> 1, wn = warp & 1;
#pragma unroll
    for (int mt = 0; mt < 2; mt++) {
        const int r0 = bm + wm * 32 + mt * 16 + (lane >> 2);
#pragma unroll
        for (int nt = 0; nt < 8; nt++) {
            const int c0 = bn + wn * 64 + nt * 8 + (lane & 3) * 2;
            const float bb0 = bias[c0], bb1 = bias[c0 + 1];
            float v00 = acc[mt][nt][0] + bb0, v01 = acc[mt][nt][1] + bb1;
            float v10 = acc[mt][nt][2] + bb0, v11 = acc[mt][nt][3] + bb1;
            if (RELU) {
                v00 = v00 > 0.f ? v00 : 0.f;  v01 = v01 > 0.f ? v01 : 0.f;
                v10 = v10 > 0.f ? v10 : 0.f;  v11 = v11 > 0.f ? v11 : 0.f;
            }
            if (WF32) {
                *(float2*)(Cf + (size_t)r0 * N + c0)       = make_float2(v00, v01);
                *(float2*)(Cf + (size_t)(r0 + 8) * N + c0) = make_float2(v10, v11);
            }
            if (NLOUT == 1) {
                *(uint32_t*)(Ch + (size_t)r0 * N + c0)       = packh2(v00, v01);
                *(uint32_t*)(Ch + (size_t)(r0 + 8) * N + c0) = packh2(v10, v11);
            }
            if (NLOUT == 2) {
                uint32_t h0, l0, h1, l1;
                splitf16(v00, v01, h0, l0);
                splitf16(v10, v11, h1, l1);
                *(uint32_t*)(Ch + (size_t)r0 * N + c0)       = h0;
                *(uint32_t*)(Ch + (size_t)(r0 + 8) * N + c0) = h1;
                *(uint32_t*)(Cl + (size_t)r0 * N + c0)       = l0;
                *(uint32_t*)(Cl + (size_t)(r0 + 8) * N + c0) = l1;
            }
        }
    }
}

// ---------------- approx distance: 128 tok x 256 codes per CTA --------------
__device__ __forceinline__ bool vless(float v, int i, float v2, int i2) {
    return v < v2 || (v == v2 && i < i2);
}
// merge top-2 pair (r0,r1) with sorted pair (p0,p1)
__device__ __forceinline__ void merge2(float& r0, int& ri0, float& r1, int& ri1,
                                       float p0, int pi0, float p1, int pi1) {
    if (vless(p0, pi0, r0, ri0)) {
        if (vless(r0, ri0, p1, pi1)) { r1 = r0; ri1 = ri0; }
        else                         { r1 = p1; ri1 = pi1; }
        r0 = p0; ri0 = pi0;
    } else {
        if (vless(p0, pi0, r1, ri1)) { r1 = p0; ri1 = pi0; }
    }
}

#define D_STG 24576            // A_L + 2*B_L  (128x32 A + 256x32 B)

__global__ __launch_bounds__(512, 1)
void tdist_kernel(const f16* __restrict__ zh, const f16* __restrict__ cbh)
{
    extern __shared__ char sm[];
    constexpr int NKT = HRDIM / 32;     // 16
    const int tid = threadIdx.x, lane = tid & 31, warp = tid >> 5;
    const int wm = warp >> 2, wn = warp & 3;     // 4x4 warp grid
    const int strip = blockIdx.x;                // 0..15
    const int bn = strip * 256, bm = blockIdx.y * 128;
    const uint32_t sb = smem_to_u32(sm);

    float acc[2][8][4];
#pragma unroll
    for (int mt = 0; mt < 2; mt++)
#pragma unroll
        for (int nt = 0; nt < 8; nt++)
#pragma unroll
            for (int q = 0; q < 4; q++) acc[mt][nt][q] = 0.f;

    // stage loader: A 512 chunks (1/thread), B 1024 chunks (2/thread)
    auto issue = [&](int t, int slot) {
        const uint32_t ss = sb + slot * D_STG;
        const int k0 = t * 32;
        {
            const int row = tid >> 2, ch = tid & 3;
            cp16(ss + swz(row, ch),
                 (const char*)(zh + (size_t)(bm + row) * HRDIM + k0) + ch * 16);
        }
#pragma unroll
        for (int i = 0; i < 2; i++) {
            const int id = tid + i * 512;
            const int row = id >> 2, ch = id & 3;
            cp16(ss + A_L + swz(row, ch),
                 (const char*)(cbh + (size_t)(bn + row) * HRDIM + k0) + ch * 16);
        }
    };

    issue(0, 0); CP_COMMIT();
    issue(1, 1); CP_COMMIT();
    issue(2, 2); CP_COMMIT();

    const int arow = lane & 15, ach = lane >> 4;
    const int brow = (lane & 7) + ((lane >> 4) << 3), bch = (lane >> 3) & 1;

    for (int t = 0; t < NKT; t++) {
        CP_WAIT2();
        __syncthreads();
        if (t + 3 < NKT) issue(t + 3, (t + 3) & 3);
        CP_COMMIT();
        const uint32_t ss = sb + (t & 3) * D_STG;
#pragma unroll
        for (int ks = 0; ks < 2; ks++) {
            uint32_t af[2][4];
#pragma unroll
            for (int mt = 0; mt < 2; mt++)
                ldm4(af[mt], ss + swz(wm * 32 + mt * 16 + arow, ks * 2 + ach));
            uint32_t bf[4][4];
#pragma unroll
            for (int np = 0; np < 4; np++)
                ldm4(bf[np], ss + A_L + swz(wn * 64 + np * 16 + brow, ks * 2 + bch));
#pragma unroll
            for (int mt = 0; mt < 2; mt++)
#pragma unroll
                for (int nt = 0; nt < 8; nt++)
                    mma16816(acc[mt][nt], af[mt], &bf[nt >> 1][(nt & 1) * 2]);
        }
    }

    // per-thread top-2 per row-slot
    float t0[4], t1[4];
    int   ti0[4], ti1[4];
#pragma unroll
    for (int s = 0; s < 4; s++) { t0[s] = t1[s] = 3.4e38f; ti0[s] = ti1[s] = 0x7fffffff; }

#pragma unroll
    for (int mt = 0; mt < 2; mt++) {
#pragma unroll
        for (int nt = 0; nt < 8; nt++) {
            const int c0 = bn + wn * 64 + nt * 8 + (lane & 3) * 2;
            const float cn0 = g_cnorm[c0], cn1 = g_cnorm[c0 + 1];
            const float sc[4] = { cn0 - 2.f * acc[mt][nt][0], cn1 - 2.f * acc[mt][nt][1],
                                  cn0 - 2.f * acc[mt][nt][2], cn1 - 2.f * acc[mt][nt][3] };
            const int   ci[4] = { c0, c0 + 1, c0, c0 + 1 };
#pragma unroll
            for (int q = 0; q < 4; q++) {
                const int s = 2 * mt + (q >> 1);
                const float v = sc[q]; const int i = ci[q];
                if (vless(v, i, t0[s], ti0[s])) {
                    t1[s] = t0[s]; ti1[s] = ti0[s]; t0[s] = v; ti0[s] = i;
                } else if (vless(v, i, t1[s], ti1[s])) {
                    t1[s] = v; ti1[s] = i;
                }
            }
        }
    }
    // merge across the 4 lanes sharing each row
#pragma unroll
    for (int d = 1; d < 4; d <<= 1) {
#pragma unroll
        for (int s = 0; s < 4; s++) {
            float ov0 = __shfl_xor_sync(0xffffffffu, t0[s], d);
            int   oi0 = __shfl_xor_sync(0xffffffffu, ti0[s], d);
            float ov1 = __shfl_xor_sync(0xffffffffu, t1[s], d);
            int   oi1 = __shfl_xor_sync(0xffffffffu, ti1[s], d);
            merge2(t0[s], ti0[s], t1[s], ti1[s], ov0, oi0, ov1, oi1);
        }
    }
    __syncthreads();               // ring smem now reusable
    float* sv0 = (float*)sm;                  // [4][128]
    float* sv1 = sv0 + 512;
    int*   si0 = (int*)(sv1 + 512);
    int*   si1 = si0 + 512;
    if ((lane & 3) == 0) {
#pragma unroll
        for (int s = 0; s < 4; s++) {
            const int rloc = wm * 32 + (s >> 1) * 16 + (s & 1) * 8 + (lane >> 2);
            sv0[wn * 128 + rloc] = t0[s];  si0[wn * 128 + rloc] = ti0[s];
            sv1[wn * 128 + rloc] = t1[s];  si1[wn * 128 + rloc] = ti1[s];
        }
    }
    __syncthreads();
    if (tid < 128) {
        float r0 = sv0[tid], r1 = sv1[tid];
        int   ri0 = si0[tid], ri1 = si1[tid];
#pragma unroll
        for (int j = 1; j < 4; j++)
            merge2(r0, ri0, r1, ri1,
                   sv0[j * 128 + tid], si0[j * 128 + tid],
                   sv1[j * 128 + tid], si1[j * 128 + tid]);
        const int tok = bm + tid;
        const size_t base = (size_t)tok * NCAND + strip * 2;
        g_pval[base] = r0;     g_pidx[base] = ri0;
        g_pval[base + 1] = r1; g_pidx[base + 1] = ri1;
    }
}

// ---------------- refine: exact fp64 rescoring of top-4 of 32 candidates ----
__global__ __launch_bounds__(256, 4)
void refine_kernel(const float* __restrict__ z, const float* __restrict__ cb)
{
    const int warp = threadIdx.x >> 5, lane = threadIdx.x & 31;
    const int tok = blockIdx.x * 8 + warp;

    float v = g_pval[(size_t)tok * NCAND + lane];
    int  id = g_pidx[(size_t)tok * NCAND + lane];

    const float* zr = z + (size_t)tok * HRDIM;
    double bestd = 1.0e300;
    int    besti = 0x7fffffff;

#pragma unroll 1
    for (int c = 0; c < 4; c++) {
        float mv = v; int mi = id;
#pragma unroll
        for (int d = 16; d > 0; d >>= 1) {
            float ov = __shfl_xor_sync(0xffffffffu, mv, d);
            int   oi = __shfl_xor_sync(0xffffffffu, mi, d);
            if (vless(ov, oi, mv, mi)) { mv = ov; mi = oi; }
        }
        if (id == mi) v = 3.4e38f;

        const float* e = cb + (size_t)mi * HRDIM;
        double acc = 0.0;
#pragma unroll
        for (int k = 0; k < HRDIM / 32; k++) {
            const int kk = lane + k * 32;
            const double df = (double)zr[kk] - (double)e[kk];
            acc += df * df;
        }
#pragma unroll
        for (int d = 16; d > 0; d >>= 1)
            acc += __shfl_xor_sync(0xffffffffu, acc, d);
        if (acc < bestd || (acc == bestd && mi < besti)) { bestd = acc; besti = mi; }
    }
    if (lane == 0) g_idx[tok] = besti;
}

// ---------------- input split: x -> 2 fp16 limb planes ----------------------
__global__ void splitx_kernel(const float4* __restrict__ in,
                              uint2* __restrict__ h, uint2* __restrict__ l)
{
    const size_t i = (size_t)blockIdx.x * 256 + threadIdx.x;
    const float4 v = in[i];
    uint32_t h0, l0, h1, l1;
    splitf16(v.x, v.y, h0, l0);
    splitf16(v.z, v.w, h1, l1);
    h[i] = make_uint2(h0, h1);
    l[i] = make_uint2(l0, l1);
}

// ---------------- codebook: norms + fp16 2-limb planes ----------------------
__global__ void cbprep_kernel(const float* __restrict__ cb,
                              uint2* __restrict__ h, uint2* __restrict__ l)
{
    __shared__ float s[128];
    const int c = blockIdx.x, t = threadIdx.x;
    const float4 v = ((const float4*)(cb + (size_t)c * HRDIM))[t];
    uint32_t h0, l0, h1, l1;
    splitf16(v.x, v.y, h0, l0);
    splitf16(v.z, v.w, h1, l1);
    const size_t o = (size_t)c * (HRDIM / 4) + t;
    h[o] = make_uint2(h0, h1);
    l[o] = make_uint2(l0, l1);
    s[t] = v.x * v.x + v.y * v.y + v.z * v.z + v.w * v.w;
    __syncthreads();
    for (int off = 64; off > 0; off >>= 1) {
        if (t < off) s[t] += s[t + off];
        __syncthreads();
    }
    if (t == 0) g_cnorm[c] = s[0];
}

// ---------------- weights: transpose + fp16 2-limb split --------------------
__global__ void transsplit_kernel(const float* __restrict__ in,
                                  f16* __restrict__ h, f16* __restrict__ l,
                                  int K, int N)
{
    __shared__ float t[32][33];
    const int n0 = blockIdx.x * 32, k0 = blockIdx.y * 32;
    const int tx = threadIdx.x, ty = threadIdx.y;
#pragma unroll
    for (int i = 0; i < 4; i++)
        t[ty + i * 8][tx] = in[(size_t)(k0 + ty + i * 8) * N + n0 + tx];
    __syncthreads();
#pragma unroll
    for (int i = 0; i < 4; i++) {
        const float a = t[tx][ty + i * 8];
        const float ha = __half2float(__float2half_rn(a));
        const size_t o = (size_t)(n0 + ty + i * 8) * K + k0 + tx;
        h[o] = __float2half_rn(ha);
        l[o] = __float2half_rn(a - ha);
    }
}

// ---------------- gather + STE + commit partials + index write --------------
__global__ void gather_kernel(const float* __restrict__ CB,
                              float* __restrict__ outq,
                              float* __restrict__ outidx)
{
    __shared__ float s[128];
    const int n = blockIdx.x;
    const int t = threadIdx.x;
    const int id = g_idx[n];

    float4 z4 = *(const float4*)(g_z + (size_t)n * HRDIM + t * 4);
    float4 q4 = *(const float4*)(CB + (size_t)id * HRDIM + t * 4);

    float4 o;
    o.x = z4.x + (q4.x - z4.x);
    o.y = z4.y + (q4.y - z4.y);
    o.z = z4.z + (q4.z - z4.z);
    o.w = z4.w + (q4.w - z4.w);
    *(float4*)(outq + (size_t)n * HRDIM + t * 4) = o;

    float dx = z4.x - q4.x, dy = z4.y - q4.y, dz = z4.z - q4.z, dw = z4.w - q4.w;
    s[t] = dx * dx + dy * dy + dz * dz + dw * dw;
    __syncthreads();
    for (int off = 64; off > 0; off >>= 1) {
        if (t < off) s[t] += s[t + off];
        __syncthreads();
    }
    if (t == 0) {
        g_part[n] = s[0];
        outidx[n] = (float)id;
    }
}

// ---------------- recon gather: out_recon[token] = cb_recon[idx[token]] -----
__global__ void recon_gather_kernel(float* __restrict__ out_recon)
{
    const int n = blockIdx.x;
    const int t = threadIdx.x;
    const int id = g_idx[n];
    const float4 v = ((const float4*)(g_crec + (size_t)id * HDIM))[t];
    ((float4*)(out_recon + (size_t)n * HDIM))[t] = v;
}

// ---------------- deterministic commit-loss sum -----------------------------
__global__ void losssum_kernel(float* __restrict__ outloss)
{
    __shared__ float s[1024];
    float acc = 0.f;
    for (int i = threadIdx.x; i < NTOK; i += 1024) acc += g_part[i];
    s[threadIdx.x] = acc;
    __syncthreads();
    for (int off = 512; off > 0; off >>= 1) {
        if (threadIdx.x < off) s[threadIdx.x] += s[threadIdx.x + off];
        __syncthreads();
    }
    if (threadIdx.x == 0)
        outloss[0] = 0.25f * s[0] / (float)((size_t)NTOK * HRDIM);
}

// ---------------- launch ----------------------------------------------------
extern "C" void kernel_launch(void* const* d_in, const int* in_sizes, int n_in,
                              void* d_out, int out_size)
{
    const float* x   = (const float*)d_in[0];
    const float* ew1 = (const float*)d_in[1];
    const float* eb1 = (const float*)d_in[2];
    const float* ew2 = (const float*)d_in[3];
    const float* eb2 = (const float*)d_in[4];
    const float* cb  = (const float*)d_in[5];
    const float* dw1 = (const float*)d_in[6];
    const float* db1 = (const float*)d_in[7];
    const float* dw2 = (const float*)d_in[8];
    const float* db2 = (const float*)d_in[9];

    float* out       = (float*)d_out;
    float* out_recon = out;
    float* out_q     = out + (size_t)NTOK * HDIM;
    float* out_idx   = out_q + (size_t)NTOK * HRDIM;
    float* out_loss  = out_idx + NTOK;

    f16 *xh, *xl, *h1h, *h1l, *zh, *cbh, *cbl, *hch, *hcl;
    f16 *w1h, *w1l, *w2h, *w2l, *w3h, *w3l, *w4h, *w4l;
    float *z, *crec;
    cudaGetSymbolAddress((void**)&xh, g_xh);   cudaGetSymbolAddress((void**)&xl, g_xl);
    cudaGetSymbolAddress((void**)&h1h, g_h1h); cudaGetSymbolAddress((void**)&h1l, g_h1l);
    cudaGetSymbolAddress((void**)&zh, g_zh);
    cudaGetSymbolAddress((void**)&cbh, g_cbh); cudaGetSymbolAddress((void**)&cbl, g_cbl);
    cudaGetSymbolAddress((void**)&hch, g_hch); cudaGetSymbolAddress((void**)&hcl, g_hcl);
    cudaGetSymbolAddress((void**)&crec, g_crec);
    cudaGetSymbolAddress((void**)&w1h, g_w1h); cudaGetSymbolAddress((void**)&w1l, g_w1l);
    cudaGetSymbolAddress((void**)&w2h, g_w2h); cudaGetSymbolAddress((void**)&w2l, g_w2l);
    cudaGetSymbolAddress((void**)&w3h, g_w3h); cudaGetSymbolAddress((void**)&w3l, g_w3l);
    cudaGetSymbolAddress((void**)&w4h, g_w4h); cudaGetSymbolAddress((void**)&w4l, g_w4l);
    cudaGetSymbolAddress((void**)&z, g_z);

    const int SM2 = 3 * 2 * (A_L + B_L);   // 98304 (NL=2 ring)
    const int SMD = 4 * D_STG;             // 98304 (4-deep dist ring)

    cudaFuncSetAttribute(tgemm_kernel<1024, 3, true,  false, 2>, cudaFuncAttributeMaxDynamicSharedMemorySize, SM2);
    cudaFuncSetAttribute(tgemm_kernel<1024, 3, false, true,  1>, cudaFuncAttributeMaxDynamicSharedMemorySize, SM2);
    cudaFuncSetAttribute(tgemm_kernel<512,  3, true,  false, 2>, cudaFuncAttributeMaxDynamicSharedMemorySize, SM2);
    cudaFuncSetAttribute(tgemm_kernel<1024, 3, false, true,  0>, cudaFuncAttributeMaxDynamicSharedMemorySize, SM2);
    cudaFuncSetAttribute(tdist_kernel, cudaFuncAttributeMaxDynamicSharedMemorySize, SMD);

    // prep: splits + codebook planes/norms
    cbprep_kernel<<<CDIM, 128>>>(cb, (uint2*)cbh, (uint2*)cbl);
    splitx_kernel<<<(NTOK * HDIM / 4) / 256, 256>>>((const float4*)x, (uint2*)xh, (uint2*)xl);
    dim3 tb(32, 8);
    transsplit_kernel<<<dim3(32, 32), tb>>>(ew1, w1h, w1l, 1024, 1024);
    transsplit_kernel<<<dim3(16, 32), tb>>>(ew2, w2h, w2l, 1024, 512);
    transsplit_kernel<<<dim3(32, 16), tb>>>(dw1, w3h, w3l, 512, 1024);
    transsplit_kernel<<<dim3(32, 32), tb>>>(dw2, w4h, w4l, 1024, 1024);

    // decoder collapsed over the 4096-entry codebook
    tgemm_kernel<512, 3, true, false, 2><<<dim3(8, CDIM / 128), 256, SM2>>>(
        cbh, cbl, w3h, w3l, db1, nullptr, hch, hcl, HDIM);
    tgemm_kernel<1024, 3, false, true, 0><<<dim3(8, CDIM / 128), 256, SM2>>>(
        hch, hcl, w4h, w4l, db2, crec, nullptr, nullptr, HDIM);

    // encoder: 3-pass fp16 2-limb
    tgemm_kernel<1024, 3, true, false, 2><<<dim3(8, NTOK / 128), 256, SM2>>>(
        xh, xl, w1h, w1l, eb1, nullptr, h1h, h1l, HDIM);
    tgemm_kernel<1024, 3, false, true, 1><<<dim3(4, NTOK / 128), 256, SM2>>>(
        h1h, h1l, w2h, w2l, eb2, z, zh, nullptr, HRDIM);

    // approx distance screening (fp16 hh, 128x256 tiles) + exact refine
    tdist_kernel<<<dim3(NSTRIP, NTOK / 128), 512, SMD>>>(zh, cbh);
    refine_kernel<<<NTOK / 8, 256>>>(z, cb);

    // quantized_st + commit partials + indices + loss
    gather_kernel<<<NTOK, 128>>>(cb, out_q, out_idx);
    losssum_kernel<<<1, 1024>>>(out_loss);

    // recon via per-code table gather
    recon_gather_kernel<<<NTOK, 256>>>(out_recon);
}